// round 12
// baseline (speedup 1.0000x reference)
#include <cuda_runtime.h>

// ---------------- problem constants ----------------
constexpr int Bn = 4;
constexpr int Sn = 4096;
constexpr int Hn = 16;
constexpr int BHn = 64;
constexpr int NSPLIT = 16;
constexpr int SCHUNK = Sn / NSPLIT;   // 256
constexpr int CH  = 64;               // s-rows per staged chunk
constexpr int NCH = SCHUNK / CH;      // 4
constexpr float PIC = 3.1415f;        // verbatim constant from reference

// ---------------- static device scratch ----------------
__device__ float    g_part  [NSPLIT * 64 * 8192];  // slot x bh x [64x128] fp32 (KV | KVp)
__device__ float    g_partKs[NSPLIT * 64 * 128];   // slot x bh x [ksum|kpsum]
__device__ unsigned g_Mst   [64 * 8192];           // bh x M/Mp-interleaved pair layout
__device__ float    g_Ks    [64 * 128];            // bh x stacked [Ksum;Kpsum] fp32

// ---------------- helpers ----------------
__device__ __forceinline__ unsigned tf32c(float f) {
    unsigned r; asm("cvt.rna.tf32.f32 %0,%1;" : "=r"(r) : "f"(f)); return r;
}
__device__ __forceinline__ void mma8(float* c,
    unsigned a0, unsigned a1, unsigned a2, unsigned a3, unsigned b0, unsigned b1)
{
    asm volatile(
        "mma.sync.aligned.m16n8k8.row.col.f32.tf32.tf32.f32 "
        "{%0,%1,%2,%3},{%4,%5,%6,%7},{%8,%9},{%0,%1,%2,%3};"
        : "+f"(c[0]), "+f"(c[1]), "+f"(c[2]), "+f"(c[3])
        : "r"(a0), "r"(a1), "r"(a2), "r"(a3), "r"(b0), "r"(b1));
}
__device__ __forceinline__ float elu1(float v) { return v > 0.f ? v + 1.f : __expf(v); }
// M/Mp interleaved pair layout: word(kk,n)+0 = M(kk,n), +1 = Mp(kk,n).
// Reader LDG.128 at uint4 index ((ks*64+n)*4 + tig) yields {M(8ks+tig), Mp(8ks+tig),
// M(8ks+tig+4), Mp(8ks+tig+4)}.
__device__ __forceinline__ int bpair2(int kk, int n) {
    return ((kk >> 3) * 64 + n) * 16 + (kk & 3) * 4 + ((kk >> 2) & 1) * 2;
}

// ===========================================================================
// Kernel 1 (tensor) — R8-proven version (clock probe; unchanged):
//   kp = elu1(rawK @ Wk_h + bk)        [mma, M64 N64 K64 per chunk]
//   C[64x128] += kp^T @ [V | sinV]     [mma, M64 N128 K64 per chunk]
// ===========================================================================
__global__ __launch_bounds__(256, 2)
void kv_kernel(const float4* __restrict__ key4, const float4* __restrict__ value4,
               const float4* __restrict__ wk_w4, const float* __restrict__ wk_b)
{
    extern __shared__ unsigned smu[];
    unsigned* sWk = smu;                  // 64 x 72   [d][n] tf32
    unsigned* sK  = sWk + 64 * 72;        // 64 x 68   [s][d] tf32
    unsigned* sV  = sK  + 64 * 68;        // 64 x 136  [s][z] tf32 (V | sinV)
    unsigned* sA  = sV  + 64 * 136;       // 64 x 76   [x][s] tf32 (kp^T), conflict-free
    float* sSin  = (float*)(sA + 64 * 76);  // 64
    float* sBias = sSin + 64;               // 64
    float* sKred = sBias + 64;              // 4 x 128

    const int bh = blockIdx.x, split = blockIdx.y;
    const int b  = bh >> 4,   h     = bh & 15;
    const int tid = threadIdx.x;
    const int lane = tid & 31, wid = tid >> 5;
    const int g = lane >> 2, tig = lane & 3;
    const int sbase = split * SCHUNK;

    // ---- stage Wk row-major [d][n] + bias ----
    #pragma unroll
    for (int t = 0; t < 4; t++) {
        int idx = tid + t * 256; int d = idx >> 4, c4 = idx & 15;
        float4 w = wk_w4[d * 256 + h * 16 + c4];
        *(uint4*)&sWk[d * 72 + c4 * 4] = make_uint4(tf32c(w.x), tf32c(w.y), tf32c(w.z), tf32c(w.w));
    }
    if (tid < 64) sBias[tid] = wk_b[h * 64 + tid];

    // ---- stage chunk 0 ----
    #pragma unroll
    for (int t = 0; t < 4; t++) {
        int idx = tid + t * 256; int r = idx >> 4, c4 = idx & 15;
        size_t gi = ((size_t)(b * Sn + sbase + r)) * 16 + c4;
        float4 k = key4[gi], v = value4[gi];
        int kb = 4 * c4;
        *(uint4*)&sK[r * 68 + kb] = make_uint4(tf32c(k.x), tf32c(k.y), tf32c(k.z), tf32c(k.w));
        float sn = __sinf(PIC * (float)(sbase + r) / (float)Sn);
        *(uint4*)&sV[r * 136 + kb]      = make_uint4(tf32c(v.x), tf32c(v.y), tf32c(v.z), tf32c(v.w));
        *(uint4*)&sV[r * 136 + 64 + kb] = make_uint4(tf32c(v.x*sn), tf32c(v.y*sn), tf32c(v.z*sn), tf32c(v.w*sn));
    }
    if (tid < 64) sSin[tid] = __sinf(PIC * (float)(sbase + tid) / (float)Sn);
    __syncthreads();

    const int m0p = (wid & 3) * 16;
    const int n0p = (wid >> 2) * 32;
    const int x0 = (wid & 1) * 32;
    const int z0 = (wid >> 1) * 32;

    float acc[2][4][4];
    #pragma unroll
    for (int i = 0; i < 2; i++)
        #pragma unroll
        for (int nt = 0; nt < 4; nt++)
            #pragma unroll
            for (int j = 0; j < 4; j++) acc[i][nt][j] = 0.f;
    float kc[4][2], kpc[4][2];
    #pragma unroll
    for (int nt = 0; nt < 4; nt++) { kc[nt][0]=kc[nt][1]=kpc[nt][0]=kpc[nt][1]=0.f; }

    for (int cc = 0; cc < NCH; cc++) {
        // ---- projection mma: kp = rawK @ Wk + bias ----
        float pc[4][4];
        #pragma unroll
        for (int nt = 0; nt < 4; nt++) {
            int col0 = n0p + 8 * nt + 2 * tig;
            pc[nt][0] = sBias[col0]; pc[nt][1] = sBias[col0 + 1];
            pc[nt][2] = sBias[col0]; pc[nt][3] = sBias[col0 + 1];
        }
        #pragma unroll
        for (int ks = 0; ks < 8; ks++) {
            int k0 = ks * 8;
            unsigned a0 = sK[(m0p + g)     * 68 + k0 + tig];
            unsigned a1 = sK[(m0p + g + 8) * 68 + k0 + tig];
            unsigned a2 = sK[(m0p + g)     * 68 + k0 + tig + 4];
            unsigned a3 = sK[(m0p + g + 8) * 68 + k0 + tig + 4];
            #pragma unroll
            for (int nt = 0; nt < 4; nt++) {
                int n = n0p + 8 * nt + g;
                unsigned b0 = sWk[(k0 + tig)     * 72 + n];
                unsigned b1 = sWk[(k0 + tig + 4) * 72 + n];
                mma8(pc[nt], a0, a1, a2, a3, b0, b1);
            }
        }

        // ---- elu + store kp^T to sA[x][s] + ksum FMA ----
        {
            int s1 = m0p + g, s2 = m0p + g + 8;
            float sn1 = sSin[s1], sn2 = sSin[s2];
            #pragma unroll
            for (int nt = 0; nt < 4; nt++) {
                int col0 = n0p + 8 * nt + 2 * tig;
                float v00 = elu1(pc[nt][0]), v01 = elu1(pc[nt][1]);
                float v10 = elu1(pc[nt][2]), v11 = elu1(pc[nt][3]);
                kc [nt][0] += v00 + v10;           kc [nt][1] += v01 + v11;
                kpc[nt][0] += v00*sn1 + v10*sn2;   kpc[nt][1] += v01*sn1 + v11*sn2;
                sA[(col0)     * 76 + s1] = tf32c(v00);
                sA[(col0 + 1) * 76 + s1] = tf32c(v01);
                sA[(col0)     * 76 + s2] = tf32c(v10);
                sA[(col0 + 1) * 76 + s2] = tf32c(v11);
            }
        }
        __syncthreads();

        // ---- accumulation mma: C[x][z] += kp^T @ [V|sinV] ----
        #pragma unroll
        for (int ks = 0; ks < 8; ks++) {
            int k0 = ks * 8;
            unsigned a[2][4];
            #pragma unroll
            for (int i = 0; i < 2; i++) {
                int xr = x0 + 16 * i + g;
                a[i][0] = sA[xr       * 76 + k0 + tig];
                a[i][1] = sA[(xr + 8) * 76 + k0 + tig];
                a[i][2] = sA[xr       * 76 + k0 + tig + 4];
                a[i][3] = sA[(xr + 8) * 76 + k0 + tig + 4];
            }
            #pragma unroll
            for (int nt = 0; nt < 4; nt++) {
                int z = z0 + 8 * nt + g;
                unsigned b0 = sV[(k0 + tig)     * 136 + z];
                unsigned b1 = sV[(k0 + tig + 4) * 136 + z];
                #pragma unroll
                for (int i = 0; i < 2; i++)
                    mma8(acc[i][nt], a[i][0], a[i][1], a[i][2], a[i][3], b0, b1);
            }
        }
        __syncthreads();

        // ---- restage next chunk ----
        if (cc + 1 < NCH) {
            int scs = sbase + (cc + 1) * CH;
            #pragma unroll
            for (int t = 0; t < 4; t++) {
                int idx = tid + t * 256; int r = idx >> 4, c4 = idx & 15;
                size_t gi = ((size_t)(b * Sn + scs + r)) * 16 + c4;
                float4 k = key4[gi], v = value4[gi];
                int kb = 4 * c4;
                *(uint4*)&sK[r * 68 + kb] = make_uint4(tf32c(k.x), tf32c(k.y), tf32c(k.z), tf32c(k.w));
                float sn = __sinf(PIC * (float)(scs + r) / (float)Sn);
                *(uint4*)&sV[r * 136 + kb]      = make_uint4(tf32c(v.x), tf32c(v.y), tf32c(v.z), tf32c(v.w));
                *(uint4*)&sV[r * 136 + 64 + kb] = make_uint4(tf32c(v.x*sn), tf32c(v.y*sn), tf32c(v.z*sn), tf32c(v.w*sn));
            }
            if (tid < 64) sSin[tid] = __sinf(PIC * (float)(scs + tid) / (float)Sn);
            __syncthreads();
        }
    }

    // ---- write fp32 C partials ----
    {
        size_t base = ((size_t)(split * 64 + bh)) * 8192;
        #pragma unroll
        for (int i = 0; i < 2; i++)
            #pragma unroll
            for (int nt = 0; nt < 4; nt++) {
                int x = x0 + 16 * i + g;
                int z = z0 + 8 * nt + 2 * tig;
                *(float2*)&g_part[base + (size_t)x       * 128 + z] = make_float2(acc[i][nt][0], acc[i][nt][1]);
                *(float2*)&g_part[base + (size_t)(x + 8) * 128 + z] = make_float2(acc[i][nt][2], acc[i][nt][3]);
            }
    }

    // ---- ksum reduce ----
    #pragma unroll
    for (int off = 4; off <= 16; off <<= 1)
        #pragma unroll
        for (int nt = 0; nt < 4; nt++)
            #pragma unroll
            for (int e = 0; e < 2; e++) {
                kc [nt][e] += __shfl_xor_sync(0xffffffffu, kc [nt][e], off);
                kpc[nt][e] += __shfl_xor_sync(0xffffffffu, kpc[nt][e], off);
            }
    if (g == 0) {
        int mt = wid & 3;
        #pragma unroll
        for (int nt = 0; nt < 4; nt++)
            #pragma unroll
            for (int e = 0; e < 2; e++) {
                int x = n0p + 8 * nt + 2 * tig + e;
                sKred[mt * 128 + x]      = kc [nt][e];
                sKred[mt * 128 + 64 + x] = kpc[nt][e];
            }
    }
    __syncthreads();
    if (tid < 128)
        g_partKs[(split * 64 + bh) * 128 + tid] =
            sKred[tid] + sKred[128 + tid] + sKred[256 + tid] + sKred[384 + tid];
}

// ===========================================================================
// Kernel 2: per bh — reduce partials, fold V-proj + dense (unchanged):
//   M/Mp = Cstk @ G + Ksum (outer) bvd -> g_Mst, M/Mp INTERLEAVED pair layout
// ===========================================================================
constexpr int PAD = 68;
__global__ __launch_bounds__(256)
void mprep_kernel(const float* __restrict__ wv_w, const float* __restrict__ wv_b,
                  const float* __restrict__ dense_w)
{
    extern __shared__ float sm[];
    float* sC    = sm;                   // 128*68 (stacked rows [KV;KVp])
    float* sWv   = sC   + 128 * PAD;     // 64*68
    float* sWd   = sWv  + 64 * PAD;      // 64*68
    float* sG    = sWd  + 64 * PAD;      // 64*68
    float* sKsum = sG   + 64 * PAD;      // 128
    float* sBvd  = sKsum + 128;          // 64
    const float4* g_part4 = (const float4*)g_part;

    const int bh = blockIdx.x, h = bh & 15, tid = threadIdx.x;

    #pragma unroll
    for (int t = 0; t < 16; t++) {
        int i = tid + t * 256; int k = i >> 6, c = i & 63;
        sWv[k * PAD + c] = wv_w[k * 1024 + h * 64 + c];
        sWd[k * PAD + c] = dense_w[(h * 64 + k) * 64 + c];
    }
    #pragma unroll
    for (int t = 0; t < 8; t++) {
        int idx = tid + t * 256;
        int x = idx >> 5, c8 = idx & 31;
        float4 s = make_float4(0.f, 0.f, 0.f, 0.f);
        for (int sl = 0; sl < NSPLIT; sl++) {
            float4 v = g_part4[((size_t)(sl * 64 + bh)) * 2048 + idx];
            s.x += v.x; s.y += v.y; s.z += v.z; s.w += v.w;
        }
        int row = (c8 < 16) ? x : (x + 64);
        int c4  = c8 & 15;
        *(float4*)&sC[row * PAD + c4 * 4] = s;
    }
    if (tid < 128) {
        float s = 0.f;
        for (int sl = 0; sl < NSPLIT; sl++) s += g_partKs[(sl * 64 + bh) * 128 + tid];
        sKsum[tid] = s;
        g_Ks[bh * 128 + tid] = s;
    }
    __syncthreads();

    const int r  = tid >> 2;
    const int c0 = (tid & 3) * 16;

    // G = Wv @ Wd
    {
        float a16[16];
        #pragma unroll
        for (int j = 0; j < 16; j++) a16[j] = 0.f;
        for (int kk = 0; kk < 64; kk++) {
            float a = sWv[r * PAD + kk];
            #pragma unroll
            for (int j = 0; j < 16; j++) a16[j] += a * sWd[kk * PAD + c0 + j];
        }
        #pragma unroll
        for (int j = 0; j < 16; j++) sG[r * PAD + c0 + j] = a16[j];
    }
    if (tid < 64) {
        float s = 0.f;
        for (int c = 0; c < 64; c++) s += wv_b[h * 64 + c] * sWd[c * PAD + tid];
        sBvd[tid] = s;
    }
    __syncthreads();

    // M/Mp = sC @ sG + ksum (outer) bvd -> g_Mst interleaved (free permute)
    {
        float m0[16], m1[16];
        #pragma unroll
        for (int j = 0; j < 16; j++) { m0[j] = 0.f; m1[j] = 0.f; }
        for (int kk = 0; kk < 64; kk++) {
            float a0 = sC[r * PAD + kk];
            float a1 = sC[(r + 64) * PAD + kk];
            #pragma unroll
            for (int j = 0; j < 16; j++) {
                float gv = sG[kk * PAD + c0 + j];
                m0[j] += a0 * gv; m1[j] += a1 * gv;
            }
        }
        float k0 = sKsum[r], k1 = sKsum[r + 64];
        #pragma unroll
        for (int j = 0; j < 16; j++) {
            m0[j] += k0 * sBvd[c0 + j];
            m1[j] += k1 * sBvd[c0 + j];
        }
        unsigned* dst = &g_Mst[(size_t)bh * 8192];
        #pragma unroll
        for (int j = 0; j < 16; j++) {
            int w0 = bpair2(r, c0 + j);   // even -> uint2-aligned
            *(uint2*)&dst[w0] = make_uint2(tf32c(m0[j]), tf32c(m1[j]));
        }
    }
}

// ===========================================================================
// Kernel 3 (tensor): per (b, 64-row s-tile), loop heads:
//   q = elu1(rawQ @ Wq_h + bq); den; o = q@M + w*(q@Mp)
//   o-GEMM B fragments read DIRECTLY from g_Mst (L2-resident) via LDG.128 —
//   no sB smem staging; smem 55KB -> 4 CTAs/SM.
// ===========================================================================
__global__ __launch_bounds__(256, 4)
void out_kernel(const float4* __restrict__ query4,
                const float4* __restrict__ wq_w4, const float* __restrict__ wq_b,
                const float* __restrict__ dense_b, float* __restrict__ out)
{
    extern __shared__ unsigned smu[];
    unsigned* sQraw = smu;                  // 64 x 68  tf32 raw Q
    unsigned* sWq   = sQraw + 64 * 68;      // 64 x 72  tf32 Wq head slice
    unsigned* sQ    = sWq   + 64 * 72;      // 64 x 68  tf32 q (elu'd)
    float* sKs  = (float*)(sQ + 64 * 68);   // 128
    float* sWs  = sKs + 128;                // 64
    float* sQb  = sWs + 64;                 // 64
    float* sDot = sQb + 64;                 // 64 x 4

    const int b  = blockIdx.y;
    const int s0 = blockIdx.x * 64;
    const int tid = threadIdx.x;
    const int lane = tid & 31, wid = tid >> 5;
    const int g = lane >> 2, tig = lane & 3;
    const int mt = wid & 3, nh = wid >> 2;
    const int m0 = mt * 16, n0 = nh * 32;

    #pragma unroll
    for (int t = 0; t < 4; t++) {
        int idx = tid + t * 256; int r = idx >> 4, c4 = idx & 15;
        float4 q = query4[((size_t)(b * Sn + s0 + r)) * 16 + c4];
        *(uint4*)&sQraw[r * 68 + c4 * 4] = make_uint4(tf32c(q.x), tf32c(q.y), tf32c(q.z), tf32c(q.w));
    }
    if (tid < 64) {
        float ps = PIC * (float)(s0 + tid) / (float)Sn;
        sWs[tid] = __cosf(ps) + __sinf(ps);
    }

    float accO[4][4];
    #pragma unroll
    for (int nt = 0; nt < 4; nt++)
        #pragma unroll
        for (int j = 0; j < 4; j++) accO[nt][j] = 0.f;
    __syncthreads();

    const uint4* __restrict__ g_Mst4 = (const uint4*)g_Mst;

    for (int h = 0; h < Hn; h++) {
        const int bh = b * 16 + h;
        #pragma unroll
        for (int t = 0; t < 4; t++) {
            int idx = tid + t * 256; int d = idx >> 4, c4 = idx & 15;
            float4 w = wq_w4[d * 256 + h * 16 + c4];
            *(uint4*)&sWq[d * 72 + c4 * 4] = make_uint4(tf32c(w.x), tf32c(w.y), tf32c(w.z), tf32c(w.w));
        }
        if (tid < 128)      sKs[tid] = g_Ks[bh * 128 + tid];
        else if (tid < 192) sQb[tid - 128] = wq_b[h * 64 + (tid - 128)];
        __syncthreads();

        // ---- q projection mma ----
        float pc[4][4];
        #pragma unroll
        for (int nt = 0; nt < 4; nt++) {
            int col0 = n0 + 8 * nt + 2 * tig;
            pc[nt][0] = sQb[col0]; pc[nt][1] = sQb[col0 + 1];
            pc[nt][2] = sQb[col0]; pc[nt][3] = sQb[col0 + 1];
        }
        #pragma unroll
        for (int ks = 0; ks < 8; ks++) {
            int k0 = ks * 8;
            unsigned a0 = sQraw[(m0 + g)     * 68 + k0 + tig];
            unsigned a1 = sQraw[(m0 + g + 8) * 68 + k0 + tig];
            unsigned a2 = sQraw[(m0 + g)     * 68 + k0 + tig + 4];
            unsigned a3 = sQraw[(m0 + g + 8) * 68 + k0 + tig + 4];
            #pragma unroll
            for (int nt = 0; nt < 4; nt++) {
                int n = n0 + 8 * nt + g;
                unsigned b0 = sWq[(k0 + tig)     * 72 + n];
                unsigned b1 = sWq[(k0 + tig + 4) * 72 + n];
                mma8(pc[nt], a0, a1, a2, a3, b0, b1);
            }
        }

        // ---- elu, partial denominators, store q (K=64) ----
        {
            int r1 = (m0 + g) * 68, r2 = (m0 + g + 8) * 68;
            float d0a = 0.f, d1a = 0.f, d0b = 0.f, d1b = 0.f;
            #pragma unroll
            for (int nt = 0; nt < 4; nt++) {
                int col0 = n0 + 8 * nt + 2 * tig;
                float ks0 = sKs[col0],      ks1 = sKs[col0 + 1];
                float kp0 = sKs[64 + col0], kp1 = sKs[64 + col0 + 1];
                float v00 = elu1(pc[nt][0]), v01 = elu1(pc[nt][1]);
                float v10 = elu1(pc[nt][2]), v11 = elu1(pc[nt][3]);
                d0a += v00 * ks0 + v01 * ks1;  d1a += v00 * kp0 + v01 * kp1;
                d0b += v10 * ks0 + v11 * ks1;  d1b += v10 * kp0 + v11 * kp1;
                sQ[r1 + col0]     = tf32c(v00);
                sQ[r1 + col0 + 1] = tf32c(v01);
                sQ[r2 + col0]     = tf32c(v10);
                sQ[r2 + col0 + 1] = tf32c(v11);
            }
            d0a += __shfl_xor_sync(0xffffffffu, d0a, 1); d0a += __shfl_xor_sync(0xffffffffu, d0a, 2);
            d1a += __shfl_xor_sync(0xffffffffu, d1a, 1); d1a += __shfl_xor_sync(0xffffffffu, d1a, 2);
            d0b += __shfl_xor_sync(0xffffffffu, d0b, 1); d0b += __shfl_xor_sync(0xffffffffu, d0b, 2);
            d1b += __shfl_xor_sync(0xffffffffu, d1b, 1); d1b += __shfl_xor_sync(0xffffffffu, d1b, 2);
            if (tig == 0) {
                sDot[(m0 + g) * 4 + nh]         = d0a;
                sDot[(m0 + g) * 4 + 2 + nh]     = d1a;
                sDot[(m0 + g + 8) * 4 + nh]     = d0b;
                sDot[(m0 + g + 8) * 4 + 2 + nh] = d1b;
            }
        }
        __syncthreads();

        int r1 = m0 + g, r2 = m0 + g + 8;
        float w1 = sWs[r1], w2 = sWs[r2];
        float den1 = 1.0f / (sDot[r1 * 4] + sDot[r1 * 4 + 1]
                     + w1 * (sDot[r1 * 4 + 2] + sDot[r1 * 4 + 3]) + 1e-5f);
        float den2 = 1.0f / (sDot[r2 * 4] + sDot[r2 * 4 + 1]
                     + w2 * (sDot[r2 * 4 + 2] + sDot[r2 * 4 + 3]) + 1e-5f);
        float dnw1 = den1 * w1, dnw2 = den2 * w2;

        // ---- split o-GEMM: ocM = q@M, ocP = q@Mp; B via direct LDG.128 from L2 ----
        float ocM[4][4], ocP[4][4];
        #pragma unroll
        for (int nt = 0; nt < 4; nt++)
            #pragma unroll
            for (int j = 0; j < 4; j++) { ocM[nt][j] = 0.f; ocP[nt][j] = 0.f; }
        const uint4* __restrict__ bb_base = g_Mst4 + (size_t)bh * 2048;
        #pragma unroll
        for (int ks = 0; ks < 8; ks++) {
            int k0 = ks * 8;
            unsigned a0 = sQ[(m0 + g)     * 68 + k0 + tig];
            unsigned a1 = sQ[(m0 + g + 8) * 68 + k0 + tig];
            unsigned a2 = sQ[(m0 + g)     * 68 + k0 + tig + 4];
            unsigned a3 = sQ[(m0 + g + 8) * 68 + k0 + tig + 4];
            #pragma unroll
            for (int nt = 0; nt < 4; nt++) {
                int n = n0 + 8 * nt + g;
                uint4 bb = bb_base[(ks * 64 + n) * 4 + tig];
                mma8(ocM[nt], a0, a1, a2, a3, bb.x, bb.z);
                mma8(ocP[nt], a0, a1, a2, a3, bb.y, bb.w);
            }
        }
        #pragma unroll
        for (int nt = 0; nt < 4; nt++) {
            accO[nt][0] += den1 * ocM[nt][0] + dnw1 * ocP[nt][0];
            accO[nt][1] += den1 * ocM[nt][1] + dnw1 * ocP[nt][1];
            accO[nt][2] += den2 * ocM[nt][2] + dnw2 * ocP[nt][2];
            accO[nt][3] += den2 * ocM[nt][3] + dnw2 * ocP[nt][3];
        }
        __syncthreads();
    }

    // ---- epilogue: + dense_b ----
    #pragma unroll
    for (int nt = 0; nt < 4; nt++) {
        int col0 = n0 + 8 * nt + 2 * tig;
        float db0 = dense_b[col0], db1 = dense_b[col0 + 1];
        size_t o1 = ((size_t)(b * Sn + s0 + m0 + g)) * 64 + col0;
        size_t o2 = ((size_t)(b * Sn + s0 + m0 + g + 8)) * 64 + col0;
        out[o1]     = accO[nt][0] + db0;
        out[o1 + 1] = accO[nt][1] + db1;
        out[o2]     = accO[nt][2] + db0;
        out[o2 + 1] = accO[nt][3] + db1;
    }
}

// ---------------------------------------------------------------------------
extern "C" void kernel_launch(void* const* d_in, const int* in_sizes, int n_in,
                              void* d_out, int out_size)
{
    const float4* query4  = (const float4*)d_in[0];
    const float4* key4    = (const float4*)d_in[1];
    const float4* value4  = (const float4*)d_in[2];
    // d_in[3] = attn_mask (unused by the math)
    const float4* wq_w4   = (const float4*)d_in[4];
    const float*  wq_b    = (const float*)d_in[5];
    const float4* wk_w4   = (const float4*)d_in[6];
    const float*  wk_b    = (const float*)d_in[7];
    const float*  wv_w    = (const float*)d_in[8];
    const float*  wv_b    = (const float*)d_in[9];
    const float*  dense_w = (const float*)d_in[10];
    const float*  dense_b = (const float*)d_in[11];
    float* out = (float*)d_out;

    constexpr int SM_KV  = (64*72 + 64*68 + 64*136 + 64*76 + 64 + 64 + 512) * 4;  // 95,232 B
    constexpr int SM_MP  = (128 * PAD + 3 * 64 * PAD + 128 + 64) * 4;             // 87,808 B
    constexpr int SM_OUT = (64*68 + 64*72 + 64*68 + 128 + 64 + 64 + 256) * 4;     // 55,296 B

    cudaFuncSetAttribute(kv_kernel,    cudaFuncAttributeMaxDynamicSharedMemorySize, SM_KV);
    cudaFuncSetAttribute(mprep_kernel, cudaFuncAttributeMaxDynamicSharedMemorySize, SM_MP);
    cudaFuncSetAttribute(out_kernel,   cudaFuncAttributeMaxDynamicSharedMemorySize, SM_OUT);

    kv_kernel   <<<dim3(BHn, NSPLIT), 256, SM_KV >>>(key4, value4, wk_w4, wk_b);
    mprep_kernel<<<BHn,               256, SM_MP >>>(wv_w, wv_b, dense_w);
    out_kernel  <<<dim3(Sn / 64, Bn), 256, SM_OUT>>>(query4, wq_w4, wq_b, dense_b, out);
}

// round 13
// speedup vs baseline: 1.1477x; 1.1477x over previous
#include <cuda_runtime.h>

// ---------------- problem constants ----------------
constexpr int Bn = 4;
constexpr int Sn = 4096;
constexpr int Hn = 16;
constexpr int BHn = 64;
constexpr int NSPLIT = 16;
constexpr int SCHUNK = Sn / NSPLIT;   // 256
constexpr int CH  = 64;               // s-rows per staged chunk
constexpr int NCH = SCHUNK / CH;      // 4
constexpr float PIC = 3.1415f;        // verbatim constant from reference

// ---------------- static device scratch ----------------
__device__ float    g_part  [NSPLIT * 64 * 8192];  // slot x bh x [64x128] fp32 (KV | KVp)
__device__ float    g_partKs[NSPLIT * 64 * 128];   // slot x bh x [ksum|kpsum]
__device__ unsigned g_Mst   [64 * 8192];           // bh x M/Mp-interleaved pair layout
__device__ float    g_Ks    [64 * 128];            // bh x stacked [Ksum;Kpsum] fp32

// ---------------- helpers ----------------
__device__ __forceinline__ unsigned tf32c(float f) {
    unsigned r; asm("cvt.rna.tf32.f32 %0,%1;" : "=r"(r) : "f"(f)); return r;
}
__device__ __forceinline__ void mma8(float* c,
    unsigned a0, unsigned a1, unsigned a2, unsigned a3, unsigned b0, unsigned b1)
{
    asm volatile(
        "mma.sync.aligned.m16n8k8.row.col.f32.tf32.tf32.f32 "
        "{%0,%1,%2,%3},{%4,%5,%6,%7},{%8,%9},{%0,%1,%2,%3};"
        : "+f"(c[0]), "+f"(c[1]), "+f"(c[2]), "+f"(c[3])
        : "r"(a0), "r"(a1), "r"(a2), "r"(a3), "r"(b0), "r"(b1));
}
__device__ __forceinline__ float elu1(float v) { return v > 0.f ? v + 1.f : __expf(v); }
// M/Mp interleaved pair layout: word(kk,n)+0 = M(kk,n), +1 = Mp(kk,n).
// Reader LDS.128 at ((ks*64+n)*16 + 4*tig) yields {M(8ks+tig), Mp(8ks+tig),
// M(8ks+tig+4), Mp(8ks+tig+4)}. Conflict-free.
__device__ __forceinline__ int bpair2(int kk, int n) {
    return ((kk >> 3) * 64 + n) * 16 + (kk & 3) * 4 + ((kk >> 2) & 1) * 2;
}

// ===========================================================================
// Kernel 1 (tensor) — R8-proven version (clock probe; unchanged):
//   kp = elu1(rawK @ Wk_h + bk)        [mma, M64 N64 K64 per chunk]
//   C[64x128] += kp^T @ [V | sinV]     [mma, M64 N128 K64 per chunk]
// ===========================================================================
__global__ __launch_bounds__(256, 2)
void kv_kernel(const float4* __restrict__ key4, const float4* __restrict__ value4,
               const float4* __restrict__ wk_w4, const float* __restrict__ wk_b)
{
    extern __shared__ unsigned smu[];
    unsigned* sWk = smu;                  // 64 x 72   [d][n] tf32
    unsigned* sK  = sWk + 64 * 72;        // 64 x 68   [s][d] tf32
    unsigned* sV  = sK  + 64 * 68;        // 64 x 136  [s][z] tf32 (V | sinV)
    unsigned* sA  = sV  + 64 * 136;       // 64 x 76   [x][s] tf32 (kp^T), conflict-free
    float* sSin  = (float*)(sA + 64 * 76);  // 64
    float* sBias = sSin + 64;               // 64
    float* sKred = sBias + 64;              // 4 x 128

    const int bh = blockIdx.x, split = blockIdx.y;
    const int b  = bh >> 4,   h     = bh & 15;
    const int tid = threadIdx.x;
    const int lane = tid & 31, wid = tid >> 5;
    const int g = lane >> 2, tig = lane & 3;
    const int sbase = split * SCHUNK;

    // ---- stage Wk row-major [d][n] + bias ----
    #pragma unroll
    for (int t = 0; t < 4; t++) {
        int idx = tid + t * 256; int d = idx >> 4, c4 = idx & 15;
        float4 w = wk_w4[d * 256 + h * 16 + c4];
        *(uint4*)&sWk[d * 72 + c4 * 4] = make_uint4(tf32c(w.x), tf32c(w.y), tf32c(w.z), tf32c(w.w));
    }
    if (tid < 64) sBias[tid] = wk_b[h * 64 + tid];

    // ---- stage chunk 0 ----
    #pragma unroll
    for (int t = 0; t < 4; t++) {
        int idx = tid + t * 256; int r = idx >> 4, c4 = idx & 15;
        size_t gi = ((size_t)(b * Sn + sbase + r)) * 16 + c4;
        float4 k = key4[gi], v = value4[gi];
        int kb = 4 * c4;
        *(uint4*)&sK[r * 68 + kb] = make_uint4(tf32c(k.x), tf32c(k.y), tf32c(k.z), tf32c(k.w));
        float sn = __sinf(PIC * (float)(sbase + r) / (float)Sn);
        *(uint4*)&sV[r * 136 + kb]      = make_uint4(tf32c(v.x), tf32c(v.y), tf32c(v.z), tf32c(v.w));
        *(uint4*)&sV[r * 136 + 64 + kb] = make_uint4(tf32c(v.x*sn), tf32c(v.y*sn), tf32c(v.z*sn), tf32c(v.w*sn));
    }
    if (tid < 64) sSin[tid] = __sinf(PIC * (float)(sbase + tid) / (float)Sn);
    __syncthreads();

    const int m0p = (wid & 3) * 16;
    const int n0p = (wid >> 2) * 32;
    const int x0 = (wid & 1) * 32;
    const int z0 = (wid >> 1) * 32;

    float acc[2][4][4];
    #pragma unroll
    for (int i = 0; i < 2; i++)
        #pragma unroll
        for (int nt = 0; nt < 4; nt++)
            #pragma unroll
            for (int j = 0; j < 4; j++) acc[i][nt][j] = 0.f;
    float kc[4][2], kpc[4][2];
    #pragma unroll
    for (int nt = 0; nt < 4; nt++) { kc[nt][0]=kc[nt][1]=kpc[nt][0]=kpc[nt][1]=0.f; }

    for (int cc = 0; cc < NCH; cc++) {
        // ---- projection mma: kp = rawK @ Wk + bias ----
        float pc[4][4];
        #pragma unroll
        for (int nt = 0; nt < 4; nt++) {
            int col0 = n0p + 8 * nt + 2 * tig;
            pc[nt][0] = sBias[col0]; pc[nt][1] = sBias[col0 + 1];
            pc[nt][2] = sBias[col0]; pc[nt][3] = sBias[col0 + 1];
        }
        #pragma unroll
        for (int ks = 0; ks < 8; ks++) {
            int k0 = ks * 8;
            unsigned a0 = sK[(m0p + g)     * 68 + k0 + tig];
            unsigned a1 = sK[(m0p + g + 8) * 68 + k0 + tig];
            unsigned a2 = sK[(m0p + g)     * 68 + k0 + tig + 4];
            unsigned a3 = sK[(m0p + g + 8) * 68 + k0 + tig + 4];
            #pragma unroll
            for (int nt = 0; nt < 4; nt++) {
                int n = n0p + 8 * nt + g;
                unsigned b0 = sWk[(k0 + tig)     * 72 + n];
                unsigned b1 = sWk[(k0 + tig + 4) * 72 + n];
                mma8(pc[nt], a0, a1, a2, a3, b0, b1);
            }
        }

        // ---- elu + store kp^T to sA[x][s] + ksum FMA ----
        {
            int s1 = m0p + g, s2 = m0p + g + 8;
            float sn1 = sSin[s1], sn2 = sSin[s2];
            #pragma unroll
            for (int nt = 0; nt < 4; nt++) {
                int col0 = n0p + 8 * nt + 2 * tig;
                float v00 = elu1(pc[nt][0]), v01 = elu1(pc[nt][1]);
                float v10 = elu1(pc[nt][2]), v11 = elu1(pc[nt][3]);
                kc [nt][0] += v00 + v10;           kc [nt][1] += v01 + v11;
                kpc[nt][0] += v00*sn1 + v10*sn2;   kpc[nt][1] += v01*sn1 + v11*sn2;
                sA[(col0)     * 76 + s1] = tf32c(v00);
                sA[(col0 + 1) * 76 + s1] = tf32c(v01);
                sA[(col0)     * 76 + s2] = tf32c(v10);
                sA[(col0 + 1) * 76 + s2] = tf32c(v11);
            }
        }
        __syncthreads();

        // ---- accumulation mma: C[x][z] += kp^T @ [V|sinV] ----
        #pragma unroll
        for (int ks = 0; ks < 8; ks++) {
            int k0 = ks * 8;
            unsigned a[2][4];
            #pragma unroll
            for (int i = 0; i < 2; i++) {
                int xr = x0 + 16 * i + g;
                a[i][0] = sA[xr       * 76 + k0 + tig];
                a[i][1] = sA[(xr + 8) * 76 + k0 + tig];
                a[i][2] = sA[xr       * 76 + k0 + tig + 4];
                a[i][3] = sA[(xr + 8) * 76 + k0 + tig + 4];
            }
            #pragma unroll
            for (int nt = 0; nt < 4; nt++) {
                int z = z0 + 8 * nt + g;
                unsigned b0 = sV[(k0 + tig)     * 136 + z];
                unsigned b1 = sV[(k0 + tig + 4) * 136 + z];
                #pragma unroll
                for (int i = 0; i < 2; i++)
                    mma8(acc[i][nt], a[i][0], a[i][1], a[i][2], a[i][3], b0, b1);
            }
        }
        __syncthreads();

        // ---- restage next chunk ----
        if (cc + 1 < NCH) {
            int scs = sbase + (cc + 1) * CH;
            #pragma unroll
            for (int t = 0; t < 4; t++) {
                int idx = tid + t * 256; int r = idx >> 4, c4 = idx & 15;
                size_t gi = ((size_t)(b * Sn + scs + r)) * 16 + c4;
                float4 k = key4[gi], v = value4[gi];
                int kb = 4 * c4;
                *(uint4*)&sK[r * 68 + kb] = make_uint4(tf32c(k.x), tf32c(k.y), tf32c(k.z), tf32c(k.w));
                float sn = __sinf(PIC * (float)(scs + r) / (float)Sn);
                *(uint4*)&sV[r * 136 + kb]      = make_uint4(tf32c(v.x), tf32c(v.y), tf32c(v.z), tf32c(v.w));
                *(uint4*)&sV[r * 136 + 64 + kb] = make_uint4(tf32c(v.x*sn), tf32c(v.y*sn), tf32c(v.z*sn), tf32c(v.w*sn));
            }
            if (tid < 64) sSin[tid] = __sinf(PIC * (float)(scs + tid) / (float)Sn);
            __syncthreads();
        }
    }

    // ---- write fp32 C partials ----
    {
        size_t base = ((size_t)(split * 64 + bh)) * 8192;
        #pragma unroll
        for (int i = 0; i < 2; i++)
            #pragma unroll
            for (int nt = 0; nt < 4; nt++) {
                int x = x0 + 16 * i + g;
                int z = z0 + 8 * nt + 2 * tig;
                *(float2*)&g_part[base + (size_t)x       * 128 + z] = make_float2(acc[i][nt][0], acc[i][nt][1]);
                *(float2*)&g_part[base + (size_t)(x + 8) * 128 + z] = make_float2(acc[i][nt][2], acc[i][nt][3]);
            }
    }

    // ---- ksum reduce ----
    #pragma unroll
    for (int off = 4; off <= 16; off <<= 1)
        #pragma unroll
        for (int nt = 0; nt < 4; nt++)
            #pragma unroll
            for (int e = 0; e < 2; e++) {
                kc [nt][e] += __shfl_xor_sync(0xffffffffu, kc [nt][e], off);
                kpc[nt][e] += __shfl_xor_sync(0xffffffffu, kpc[nt][e], off);
            }
    if (g == 0) {
        int mt = wid & 3;
        #pragma unroll
        for (int nt = 0; nt < 4; nt++)
            #pragma unroll
            for (int e = 0; e < 2; e++) {
                int x = n0p + 8 * nt + 2 * tig + e;
                sKred[mt * 128 + x]      = kc [nt][e];
                sKred[mt * 128 + 64 + x] = kpc[nt][e];
            }
    }
    __syncthreads();
    if (tid < 128)
        g_partKs[(split * 64 + bh) * 128 + tid] =
            sKred[tid] + sKred[128 + tid] + sKred[256 + tid] + sKred[384 + tid];
}

// ===========================================================================
// Kernel 2: per bh — reduce partials, fold V-proj + dense (unchanged):
//   M/Mp = Cstk @ G + Ksum (outer) bvd -> g_Mst, M/Mp INTERLEAVED pair layout
// ===========================================================================
constexpr int PAD = 68;
__global__ __launch_bounds__(256)
void mprep_kernel(const float* __restrict__ wv_w, const float* __restrict__ wv_b,
                  const float* __restrict__ dense_w)
{
    extern __shared__ float sm[];
    float* sC    = sm;                   // 128*68 (stacked rows [KV;KVp])
    float* sWv   = sC   + 128 * PAD;     // 64*68
    float* sWd   = sWv  + 64 * PAD;      // 64*68
    float* sG    = sWd  + 64 * PAD;      // 64*68
    float* sKsum = sG   + 64 * PAD;      // 128
    float* sBvd  = sKsum + 128;          // 64
    const float4* g_part4 = (const float4*)g_part;

    const int bh = blockIdx.x, h = bh & 15, tid = threadIdx.x;

    #pragma unroll
    for (int t = 0; t < 16; t++) {
        int i = tid + t * 256; int k = i >> 6, c = i & 63;
        sWv[k * PAD + c] = wv_w[k * 1024 + h * 64 + c];
        sWd[k * PAD + c] = dense_w[(h * 64 + k) * 64 + c];
    }
    #pragma unroll
    for (int t = 0; t < 8; t++) {
        int idx = tid + t * 256;
        int x = idx >> 5, c8 = idx & 31;
        float4 s = make_float4(0.f, 0.f, 0.f, 0.f);
        for (int sl = 0; sl < NSPLIT; sl++) {
            float4 v = g_part4[((size_t)(sl * 64 + bh)) * 2048 + idx];
            s.x += v.x; s.y += v.y; s.z += v.z; s.w += v.w;
        }
        int row = (c8 < 16) ? x : (x + 64);
        int c4  = c8 & 15;
        *(float4*)&sC[row * PAD + c4 * 4] = s;
    }
    if (tid < 128) {
        float s = 0.f;
        for (int sl = 0; sl < NSPLIT; sl++) s += g_partKs[(sl * 64 + bh) * 128 + tid];
        sKsum[tid] = s;
        g_Ks[bh * 128 + tid] = s;
    }
    __syncthreads();

    const int r  = tid >> 2;
    const int c0 = (tid & 3) * 16;

    // G = Wv @ Wd
    {
        float a16[16];
        #pragma unroll
        for (int j = 0; j < 16; j++) a16[j] = 0.f;
        for (int kk = 0; kk < 64; kk++) {
            float a = sWv[r * PAD + kk];
            #pragma unroll
            for (int j = 0; j < 16; j++) a16[j] += a * sWd[kk * PAD + c0 + j];
        }
        #pragma unroll
        for (int j = 0; j < 16; j++) sG[r * PAD + c0 + j] = a16[j];
    }
    if (tid < 64) {
        float s = 0.f;
        for (int c = 0; c < 64; c++) s += wv_b[h * 64 + c] * sWd[c * PAD + tid];
        sBvd[tid] = s;
    }
    __syncthreads();

    // M/Mp = sC @ sG + ksum (outer) bvd -> g_Mst interleaved (free permute)
    {
        float m0[16], m1[16];
        #pragma unroll
        for (int j = 0; j < 16; j++) { m0[j] = 0.f; m1[j] = 0.f; }
        for (int kk = 0; kk < 64; kk++) {
            float a0 = sC[r * PAD + kk];
            float a1 = sC[(r + 64) * PAD + kk];
            #pragma unroll
            for (int j = 0; j < 16; j++) {
                float gv = sG[kk * PAD + c0 + j];
                m0[j] += a0 * gv; m1[j] += a1 * gv;
            }
        }
        float k0 = sKsum[r], k1 = sKsum[r + 64];
        #pragma unroll
        for (int j = 0; j < 16; j++) {
            m0[j] += k0 * sBvd[c0 + j];
            m1[j] += k1 * sBvd[c0 + j];
        }
        unsigned* dst = &g_Mst[(size_t)bh * 8192];
        #pragma unroll
        for (int j = 0; j < 16; j++) {
            int w0 = bpair2(r, c0 + j);   // even -> uint2-aligned
            *(uint2*)&dst[w0] = make_uint2(tf32c(m0[j]), tf32c(m1[j]));
        }
    }
}

// ===========================================================================
// Kernel 3 (tensor) — R11-proven version + vectorized epilogue:
//   q = elu1(rawQ @ Wq_h + bq); den; o = q@M + w*(q@Mp)  [split GEMM, K=64,
//   both B fragments per (k,n) fetched with ONE LDS.128 from interleaved sB]
// ===========================================================================
__global__ __launch_bounds__(256, 2)
void out_kernel(const float4* __restrict__ query4,
                const float4* __restrict__ wq_w4, const float* __restrict__ wq_b,
                const float* __restrict__ dense_b, float* __restrict__ out)
{
    extern __shared__ unsigned smu[];
    unsigned* sQraw = smu;                  // 64 x 68  tf32 raw Q
    unsigned* sWq   = sQraw + 64 * 68;      // 64 x 72  tf32 Wq head slice
    unsigned* sB    = sWq   + 64 * 72;      // 8192     M/Mp interleaved pair layout
    unsigned* sQ    = sB    + 8192;         // 64 x 68  tf32 q (elu'd)
    float* sKs  = (float*)(sQ + 64 * 68);   // 128
    float* sWs  = sKs + 128;                // 64
    float* sQb  = sWs + 64;                 // 64
    float* sDot = sQb + 64;                 // 64 x 4

    const int b  = blockIdx.y;
    const int s0 = blockIdx.x * 64;
    const int tid = threadIdx.x;
    const int lane = tid & 31, wid = tid >> 5;
    const int g = lane >> 2, tig = lane & 3;
    const int mt = wid & 3, nh = wid >> 2;
    const int m0 = mt * 16, n0 = nh * 32;

    #pragma unroll
    for (int t = 0; t < 4; t++) {
        int idx = tid + t * 256; int r = idx >> 4, c4 = idx & 15;
        float4 q = query4[((size_t)(b * Sn + s0 + r)) * 16 + c4];
        *(uint4*)&sQraw[r * 68 + c4 * 4] = make_uint4(tf32c(q.x), tf32c(q.y), tf32c(q.z), tf32c(q.w));
    }
    if (tid < 64) {
        float ps = PIC * (float)(s0 + tid) / (float)Sn;
        sWs[tid] = __cosf(ps) + __sinf(ps);
    }

    float accO[4][4];
    #pragma unroll
    for (int nt = 0; nt < 4; nt++)
        #pragma unroll
        for (int j = 0; j < 4; j++) accO[nt][j] = 0.f;
    __syncthreads();

    const uint4* g_Mst4 = (const uint4*)g_Mst;

    for (int h = 0; h < Hn; h++) {
        const int bh = b * 16 + h;
        #pragma unroll
        for (int t = 0; t < 4; t++) {
            int idx = tid + t * 256; int d = idx >> 4, c4 = idx & 15;
            float4 w = wq_w4[d * 256 + h * 16 + c4];
            *(uint4*)&sWq[d * 72 + c4 * 4] = make_uint4(tf32c(w.x), tf32c(w.y), tf32c(w.z), tf32c(w.w));
        }
        #pragma unroll
        for (int t = 0; t < 8; t++) {
            int idx = tid + t * 256;
            *(uint4*)&sB[idx * 4] = g_Mst4[(size_t)bh * 2048 + idx];
        }
        if (tid < 128)      sKs[tid] = g_Ks[bh * 128 + tid];
        else if (tid < 192) sQb[tid - 128] = wq_b[h * 64 + (tid - 128)];
        __syncthreads();

        // ---- q projection mma ----
        float pc[4][4];
        #pragma unroll
        for (int nt = 0; nt < 4; nt++) {
            int col0 = n0 + 8 * nt + 2 * tig;
            pc[nt][0] = sQb[col0]; pc[nt][1] = sQb[col0 + 1];
            pc[nt][2] = sQb[col0]; pc[nt][3] = sQb[col0 + 1];
        }
        #pragma unroll
        for (int ks = 0; ks < 8; ks++) {
            int k0 = ks * 8;
            unsigned a0 = sQraw[(m0 + g)     * 68 + k0 + tig];
            unsigned a1 = sQraw[(m0 + g + 8) * 68 + k0 + tig];
            unsigned a2 = sQraw[(m0 + g)     * 68 + k0 + tig + 4];
            unsigned a3 = sQraw[(m0 + g + 8) * 68 + k0 + tig + 4];
            #pragma unroll
            for (int nt = 0; nt < 4; nt++) {
                int n = n0 + 8 * nt + g;
                unsigned b0 = sWq[(k0 + tig)     * 72 + n];
                unsigned b1 = sWq[(k0 + tig + 4) * 72 + n];
                mma8(pc[nt], a0, a1, a2, a3, b0, b1);
            }
        }

        // ---- elu, partial denominators, store q (K=64, no wq) ----
        {
            int r1 = (m0 + g) * 68, r2 = (m0 + g + 8) * 68;
            float d0a = 0.f, d1a = 0.f, d0b = 0.f, d1b = 0.f;
            #pragma unroll
            for (int nt = 0; nt < 4; nt++) {
                int col0 = n0 + 8 * nt + 2 * tig;
                float ks0 = sKs[col0],      ks1 = sKs[col0 + 1];
                float kp0 = sKs[64 + col0], kp1 = sKs[64 + col0 + 1];
                float v00 = elu1(pc[nt][0]), v01 = elu1(pc[nt][1]);
                float v10 = elu1(pc[nt][2]), v11 = elu1(pc[nt][3]);
                d0a += v00 * ks0 + v01 * ks1;  d1a += v00 * kp0 + v01 * kp1;
                d0b += v10 * ks0 + v11 * ks1;  d1b += v10 * kp0 + v11 * kp1;
                sQ[r1 + col0]     = tf32c(v00);
                sQ[r1 + col0 + 1] = tf32c(v01);
                sQ[r2 + col0]     = tf32c(v10);
                sQ[r2 + col0 + 1] = tf32c(v11);
            }
            d0a += __shfl_xor_sync(0xffffffffu, d0a, 1); d0a += __shfl_xor_sync(0xffffffffu, d0a, 2);
            d1a += __shfl_xor_sync(0xffffffffu, d1a, 1); d1a += __shfl_xor_sync(0xffffffffu, d1a, 2);
            d0b += __shfl_xor_sync(0xffffffffu, d0b, 1); d0b += __shfl_xor_sync(0xffffffffu, d0b, 2);
            d1b += __shfl_xor_sync(0xffffffffu, d1b, 1); d1b += __shfl_xor_sync(0xffffffffu, d1b, 2);
            if (tig == 0) {
                sDot[(m0 + g) * 4 + nh]         = d0a;
                sDot[(m0 + g) * 4 + 2 + nh]     = d1a;
                sDot[(m0 + g + 8) * 4 + nh]     = d0b;
                sDot[(m0 + g + 8) * 4 + 2 + nh] = d1b;
            }
        }
        __syncthreads();

        int r1 = m0 + g, r2 = m0 + g + 8;
        float w1 = sWs[r1], w2 = sWs[r2];
        float den1 = 1.0f / (sDot[r1 * 4] + sDot[r1 * 4 + 1]
                     + w1 * (sDot[r1 * 4 + 2] + sDot[r1 * 4 + 3]) + 1e-5f);
        float den2 = 1.0f / (sDot[r2 * 4] + sDot[r2 * 4 + 1]
                     + w2 * (sDot[r2 * 4 + 2] + sDot[r2 * 4 + 3]) + 1e-5f);
        float dnw1 = den1 * w1, dnw2 = den2 * w2;

        // ---- split o-GEMM: ocM = q@M, ocP = q@Mp (K=64, shared A, fused B LDS.128) ----
        float ocM[4][4], ocP[4][4];
        #pragma unroll
        for (int nt = 0; nt < 4; nt++)
            #pragma unroll
            for (int j = 0; j < 4; j++) { ocM[nt][j] = 0.f; ocP[nt][j] = 0.f; }
        #pragma unroll
        for (int ks = 0; ks < 8; ks++) {
            int k0 = ks * 8;
            unsigned a0 = sQ[(m0 + g)     * 68 + k0 + tig];
            unsigned a1 = sQ[(m0 + g + 8) * 68 + k0 + tig];
            unsigned a2 = sQ[(m0 + g)     * 68 + k0 + tig + 4];
            unsigned a3 = sQ[(m0 + g + 8) * 68 + k0 + tig + 4];
            #pragma unroll
            for (int nt = 0; nt < 4; nt++) {
                int n = n0 + 8 * nt + g;
                uint4 bb = *(const uint4*)&sB[(ks * 64 + n) * 16 + tig * 4];
                mma8(ocM[nt], a0, a1, a2, a3, bb.x, bb.z);
                mma8(ocP[nt], a0, a1, a2, a3, bb.y, bb.w);
            }
        }
        #pragma unroll
        for (int nt = 0; nt < 4; nt++) {
            accO[nt][0] += den1 * ocM[nt][0] + dnw1 * ocP[nt][0];
            accO[nt][1] += den1 * ocM[nt][1] + dnw1 * ocP[nt][1];
            accO[nt][2] += den2 * ocM[nt][2] + dnw2 * ocP[nt][2];
            accO[nt][3] += den2 * ocM[nt][3] + dnw2 * ocP[nt][3];
        }
        __syncthreads();
    }

    // ---- epilogue: + dense_b, vectorized float2 stores ----
    #pragma unroll
    for (int nt = 0; nt < 4; nt++) {
        int col0 = n0 + 8 * nt + 2 * tig;
        float2 db = *(const float2*)&dense_b[col0];
        size_t o1 = ((size_t)(b * Sn + s0 + m0 + g)) * 64 + col0;
        size_t o2 = ((size_t)(b * Sn + s0 + m0 + g + 8)) * 64 + col0;
        *(float2*)&out[o1] = make_float2(accO[nt][0] + db.x, accO[nt][1] + db.y);
        *(float2*)&out[o2] = make_float2(accO[nt][2] + db.x, accO[nt][3] + db.y);
    }
}

// ---------------------------------------------------------------------------
extern "C" void kernel_launch(void* const* d_in, const int* in_sizes, int n_in,
                              void* d_out, int out_size)
{
    const float4* query4  = (const float4*)d_in[0];
    const float4* key4    = (const float4*)d_in[1];
    const float4* value4  = (const float4*)d_in[2];
    // d_in[3] = attn_mask (unused by the math)
    const float4* wq_w4   = (const float4*)d_in[4];
    const float*  wq_b    = (const float*)d_in[5];
    const float4* wk_w4   = (const float4*)d_in[6];
    const float*  wk_b    = (const float*)d_in[7];
    const float*  wv_w    = (const float*)d_in[8];
    const float*  wv_b    = (const float*)d_in[9];
    const float*  dense_w = (const float*)d_in[10];
    const float*  dense_b = (const float*)d_in[11];
    float* out = (float*)d_out;

    constexpr int SM_KV  = (64*72 + 64*68 + 64*136 + 64*76 + 64 + 64 + 512) * 4;  // 95,232 B
    constexpr int SM_MP  = (128 * PAD + 3 * 64 * PAD + 128 + 64) * 4;             // 87,808 B
    constexpr int SM_OUT = (64*68 + 64*72 + 8192 + 64*68 + 128+64+64+256) * 4;    // 88,064 B

    cudaFuncSetAttribute(kv_kernel,    cudaFuncAttributeMaxDynamicSharedMemorySize, SM_KV);
    cudaFuncSetAttribute(mprep_kernel, cudaFuncAttributeMaxDynamicSharedMemorySize, SM_MP);
    cudaFuncSetAttribute(out_kernel,   cudaFuncAttributeMaxDynamicSharedMemorySize, SM_OUT);

    kv_kernel   <<<dim3(BHn, NSPLIT), 256, SM_KV >>>(key4, value4, wk_w4, wk_b);
    mprep_kernel<<<BHn,               256, SM_MP >>>(wv_w, wv_b, dense_w);
    out_kernel  <<<dim3(Sn / 64, Bn), 256, SM_OUT>>>(query4, wq_w4, wq_b, dense_b, out);
}

// round 14
// speedup vs baseline: 1.3248x; 1.1543x over previous
#include <cuda_runtime.h>
#include <cuda_fp16.h>

// ---------------- problem constants ----------------
constexpr int Bn = 4;
constexpr int Sn = 4096;
constexpr int Hn = 16;
constexpr int BHn = 64;
constexpr int NSPLIT = 16;
constexpr int SCHUNK = Sn / NSPLIT;   // 256
constexpr int CH  = 64;               // s-rows per staged chunk
constexpr int NCH = SCHUNK / CH;      // 4
constexpr float PIC = 3.1415f;        // verbatim constant from reference

// ---------------- static device scratch ----------------
__device__ float    g_part  [NSPLIT * 64 * 8192];  // slot x bh x [64x128] fp32 (KV | KVp)
__device__ float    g_partKs[NSPLIT * 64 * 128];   // slot x bh x [ksum|kpsum]
__device__ unsigned g_Mst   [64 * 8192];           // bh x M/Mp-interleaved pair layout (tf32)
__device__ float    g_Ks    [64 * 128];            // bh x stacked [Ksum;Kpsum] fp32

// ---------------- helpers ----------------
__device__ __forceinline__ unsigned tf32c(float f) {
    unsigned r; asm("cvt.rna.tf32.f32 %0,%1;" : "=r"(r) : "f"(f)); return r;
}
__device__ __forceinline__ void mma8(float* c,
    unsigned a0, unsigned a1, unsigned a2, unsigned a3, unsigned b0, unsigned b1)
{
    asm volatile(
        "mma.sync.aligned.m16n8k8.row.col.f32.tf32.tf32.f32 "
        "{%0,%1,%2,%3},{%4,%5,%6,%7},{%8,%9},{%0,%1,%2,%3};"
        : "+f"(c[0]), "+f"(c[1]), "+f"(c[2]), "+f"(c[3])
        : "r"(a0), "r"(a1), "r"(a2), "r"(a3), "r"(b0), "r"(b1));
}
__device__ __forceinline__ void mma16h(float* c,
    unsigned a0, unsigned a1, unsigned a2, unsigned a3, unsigned b0, unsigned b1)
{
    asm volatile(
        "mma.sync.aligned.m16n8k16.row.col.f32.f16.f16.f32 "
        "{%0,%1,%2,%3},{%4,%5,%6,%7},{%8,%9},{%0,%1,%2,%3};"
        : "+f"(c[0]), "+f"(c[1]), "+f"(c[2]), "+f"(c[3])
        : "r"(a0), "r"(a1), "r"(a2), "r"(a3), "r"(b0), "r"(b1));
}
__device__ __forceinline__ void ldsm4t(unsigned& r0, unsigned& r1, unsigned& r2, unsigned& r3,
                                       unsigned addr)
{
    asm volatile("ldmatrix.sync.aligned.m8n8.x4.trans.shared.b16 {%0,%1,%2,%3}, [%4];"
        : "=r"(r0), "=r"(r1), "=r"(r2), "=r"(r3) : "r"(addr));
}
__device__ __forceinline__ unsigned h2u(float a, float b) {
    __half2 h = __floats2half2_rn(a, b);
    return *reinterpret_cast<unsigned*>(&h);
}
__device__ __forceinline__ float elu1(float v) { return v > 0.f ? v + 1.f : __expf(v); }
// M/Mp interleaved pair layout (tf32, for out): word(kk,n)+0=M, +1=Mp.
__device__ __forceinline__ int bpair2(int kk, int n) {
    return ((kk >> 3) * 64 + n) * 16 + (kk & 3) * 4 + ((kk >> 2) & 1) * 2;
}

// ===========================================================================
// Kernel 1 (tensor, fp16 operands): per (bh, split):
//   kp = elu1(rawK @ Wk_h + bk)        [mma f16 k16; B via ldmatrix.x4.trans]
//   C[64x128] += kp^T @ [V | sinV]     [mma f16 k16; B via ldmatrix.x4.trans]
//   fp32 accumulators; ksum harvested writer-side in fp32.
// ===========================================================================
__global__ __launch_bounds__(256, 2)
void kv_kernel(const float4* __restrict__ key4, const float4* __restrict__ value4,
               const float4* __restrict__ wk_w4, const float* __restrict__ wk_b)
{
    extern __shared__ unsigned smu[];
    unsigned* hWkw = smu;                 // Wk  [k=d][n] halves, stride 72h (36w): 2304w
    unsigned* hKw  = hWkw + 2304;         // rawK [s][d] halves, stride 72h: 2304w
    unsigned* hVw  = hKw  + 2304;         // [V|sinV] [s][z] halves, stride 136h (68w): 4352w
    unsigned* hAw  = hVw  + 4352;         // kp^T [x][s] halves, stride 72h: 2304w
    float* sSin  = (float*)(hAw + 2304);  // 64
    float* sBias = sSin + 64;             // 64
    float* sKred = sBias + 64;            // 4 x 128
    __half* hAh = (__half*)hAw;

    const int bh = blockIdx.x, split = blockIdx.y;
    const int b  = bh >> 4,   h     = bh & 15;
    const int tid = threadIdx.x;
    const int lane = tid & 31, wid = tid >> 5;
    const int g = lane >> 2, tig = lane & 3;
    const int sbase = split * SCHUNK;
    // ldmatrix lane->tile geometry (t = lane>>3): rows (t&1)*8+(lane&7), cols (t>>1)*8
    const int rowp = ((lane >> 3) & 1) * 8 + (lane & 7);
    const int colp = (lane >> 4) * 8;

    const unsigned wkBase = (unsigned)__cvta_generic_to_shared(hWkw);
    const unsigned vBase  = (unsigned)__cvta_generic_to_shared(hVw);

    // ---- stage Wk [k][n] halves + bias ----
    #pragma unroll
    for (int t = 0; t < 4; t++) {
        int idx = tid + t * 256; int d = idx >> 4, c4 = idx & 15;
        float4 w = wk_w4[d * 256 + h * 16 + c4];
        *(uint2*)&hWkw[d * 36 + 2 * c4] = make_uint2(h2u(w.x, w.y), h2u(w.z, w.w));
    }
    if (tid < 64) sBias[tid] = wk_b[h * 64 + tid];

    // ---- stage chunk 0 ----
    #pragma unroll
    for (int t = 0; t < 4; t++) {
        int idx = tid + t * 256; int r = idx >> 4, c4 = idx & 15;
        size_t gi = ((size_t)(b * Sn + sbase + r)) * 16 + c4;
        float4 k = key4[gi], v = value4[gi];
        *(uint2*)&hKw[r * 36 + 2 * c4] = make_uint2(h2u(k.x, k.y), h2u(k.z, k.w));
        float sn = __sinf(PIC * (float)(sbase + r) / (float)Sn);
        *(uint2*)&hVw[r * 68 + 2 * c4]      = make_uint2(h2u(v.x, v.y), h2u(v.z, v.w));
        *(uint2*)&hVw[r * 68 + 32 + 2 * c4] = make_uint2(h2u(v.x*sn, v.y*sn), h2u(v.z*sn, v.w*sn));
    }
    if (tid < 64) sSin[tid] = __sinf(PIC * (float)(sbase + tid) / (float)Sn);
    __syncthreads();

    const int m0p = (wid & 3) * 16;
    const int n0p = (wid >> 2) * 32;
    const int x0 = (wid & 1) * 32;
    const int z0 = (wid >> 1) * 32;

    float acc[2][4][4];
    #pragma unroll
    for (int i = 0; i < 2; i++)
        #pragma unroll
        for (int nt = 0; nt < 4; nt++)
            #pragma unroll
            for (int j = 0; j < 4; j++) acc[i][nt][j] = 0.f;
    float kc[4][2], kpc[4][2];
    #pragma unroll
    for (int nt = 0; nt < 4; nt++) { kc[nt][0]=kc[nt][1]=kpc[nt][0]=kpc[nt][1]=0.f; }

    for (int cc = 0; cc < NCH; cc++) {
        // ---- projection mma (f16 k16): kp = rawK @ Wk + bias ----
        float pc[4][4];
        #pragma unroll
        for (int nt = 0; nt < 4; nt++) {
            int col0 = n0p + 8 * nt + 2 * tig;
            pc[nt][0] = sBias[col0]; pc[nt][1] = sBias[col0 + 1];
            pc[nt][2] = sBias[col0]; pc[nt][3] = sBias[col0 + 1];
        }
        #pragma unroll
        for (int ks = 0; ks < 4; ks++) {
            int kw = ks * 8;
            unsigned a0 = hKw[(m0p + g)     * 36 + kw + tig];
            unsigned a1 = hKw[(m0p + g + 8) * 36 + kw + tig];
            unsigned a2 = hKw[(m0p + g)     * 36 + kw + tig + 4];
            unsigned a3 = hKw[(m0p + g + 8) * 36 + kw + tig + 4];
            #pragma unroll
            for (int p = 0; p < 2; p++) {
                unsigned b0, b1, b2, b3;
                unsigned ad = wkBase + ((16 * ks + rowp) * 72 + n0p + 16 * p + colp) * 2;
                ldsm4t(b0, b1, b2, b3, ad);
                mma16h(pc[2 * p],     a0, a1, a2, a3, b0, b1);
                mma16h(pc[2 * p + 1], a0, a1, a2, a3, b2, b3);
            }
        }

        // ---- elu + half-store kp^T to hA[x][s] + fp32 ksum FMA ----
        {
            int s1 = m0p + g, s2 = m0p + g + 8;
            float sn1 = sSin[s1], sn2 = sSin[s2];
            #pragma unroll
            for (int nt = 0; nt < 4; nt++) {
                int col0 = n0p + 8 * nt + 2 * tig;
                float v00 = elu1(pc[nt][0]), v01 = elu1(pc[nt][1]);
                float v10 = elu1(pc[nt][2]), v11 = elu1(pc[nt][3]);
                kc [nt][0] += v00 + v10;           kc [nt][1] += v01 + v11;
                kpc[nt][0] += v00*sn1 + v10*sn2;   kpc[nt][1] += v01*sn1 + v11*sn2;
                hAh[(col0)     * 72 + s1] = __float2half_rn(v00);
                hAh[(col0 + 1) * 72 + s1] = __float2half_rn(v01);
                hAh[(col0)     * 72 + s2] = __float2half_rn(v10);
                hAh[(col0 + 1) * 72 + s2] = __float2half_rn(v11);
            }
        }
        __syncthreads();

        // ---- accumulation mma (f16 k16): C[x][z] += kp^T @ [V|sinV] ----
        #pragma unroll
        for (int ks = 0; ks < 4; ks++) {
            int kw = ks * 8;
            unsigned a[2][4];
            #pragma unroll
            for (int i = 0; i < 2; i++) {
                int xr = x0 + 16 * i + g;
                a[i][0] = hAw[xr       * 36 + kw + tig];
                a[i][1] = hAw[(xr + 8) * 36 + kw + tig];
                a[i][2] = hAw[xr       * 36 + kw + tig + 4];
                a[i][3] = hAw[(xr + 8) * 36 + kw + tig + 4];
            }
            #pragma unroll
            for (int p = 0; p < 2; p++) {
                unsigned b0, b1, b2, b3;
                unsigned ad = vBase + ((16 * ks + rowp) * 136 + z0 + 16 * p + colp) * 2;
                ldsm4t(b0, b1, b2, b3, ad);
                #pragma unroll
                for (int i = 0; i < 2; i++) {
                    mma16h(acc[i][2 * p],     a[i][0], a[i][1], a[i][2], a[i][3], b0, b1);
                    mma16h(acc[i][2 * p + 1], a[i][0], a[i][1], a[i][2], a[i][3], b2, b3);
                }
            }
        }
        __syncthreads();

        // ---- restage next chunk ----
        if (cc + 1 < NCH) {
            int scs = sbase + (cc + 1) * CH;
            #pragma unroll
            for (int t = 0; t < 4; t++) {
                int idx = tid + t * 256; int r = idx >> 4, c4 = idx & 15;
                size_t gi = ((size_t)(b * Sn + scs + r)) * 16 + c4;
                float4 k = key4[gi], v = value4[gi];
                *(uint2*)&hKw[r * 36 + 2 * c4] = make_uint2(h2u(k.x, k.y), h2u(k.z, k.w));
                float sn = __sinf(PIC * (float)(scs + r) / (float)Sn);
                *(uint2*)&hVw[r * 68 + 2 * c4]      = make_uint2(h2u(v.x, v.y), h2u(v.z, v.w));
                *(uint2*)&hVw[r * 68 + 32 + 2 * c4] = make_uint2(h2u(v.x*sn, v.y*sn), h2u(v.z*sn, v.w*sn));
            }
            if (tid < 64) sSin[tid] = __sinf(PIC * (float)(scs + tid) / (float)Sn);
            __syncthreads();
        }
    }

    // ---- write fp32 C partials: [x 0..63][z 0..127] ----
    {
        size_t base = ((size_t)(split * 64 + bh)) * 8192;
        #pragma unroll
        for (int i = 0; i < 2; i++)
            #pragma unroll
            for (int nt = 0; nt < 4; nt++) {
                int x = x0 + 16 * i + g;
                int z = z0 + 8 * nt + 2 * tig;
                *(float2*)&g_part[base + (size_t)x       * 128 + z] = make_float2(acc[i][nt][0], acc[i][nt][1]);
                *(float2*)&g_part[base + (size_t)(x + 8) * 128 + z] = make_float2(acc[i][nt][2], acc[i][nt][3]);
            }
    }

    // ---- ksum reduce ----
    #pragma unroll
    for (int off = 4; off <= 16; off <<= 1)
        #pragma unroll
        for (int nt = 0; nt < 4; nt++)
            #pragma unroll
            for (int e = 0; e < 2; e++) {
                kc [nt][e] += __shfl_xor_sync(0xffffffffu, kc [nt][e], off);
                kpc[nt][e] += __shfl_xor_sync(0xffffffffu, kpc[nt][e], off);
            }
    if (g == 0) {
        int mt = wid & 3;
        #pragma unroll
        for (int nt = 0; nt < 4; nt++)
            #pragma unroll
            for (int e = 0; e < 2; e++) {
                int x = n0p + 8 * nt + 2 * tig + e;
                sKred[mt * 128 + x]      = kc [nt][e];
                sKred[mt * 128 + 64 + x] = kpc[nt][e];
            }
    }
    __syncthreads();
    if (tid < 128)
        g_partKs[(split * 64 + bh) * 128 + tid] =
            sKred[tid] + sKred[128 + tid] + sKred[256 + tid] + sKred[384 + tid];
}

// ===========================================================================
// Kernel 2: per bh — reduce partials, fold V-proj + dense (unchanged R13):
//   M/Mp = Cstk @ G + Ksum (outer) bvd -> g_Mst, M/Mp INTERLEAVED pair layout
// ===========================================================================
constexpr int PAD = 68;
__global__ __launch_bounds__(256)
void mprep_kernel(const float* __restrict__ wv_w, const float* __restrict__ wv_b,
                  const float* __restrict__ dense_w)
{
    extern __shared__ float sm[];
    float* sC    = sm;                   // 128*68 (stacked rows [KV;KVp])
    float* sWv   = sC   + 128 * PAD;     // 64*68
    float* sWd   = sWv  + 64 * PAD;      // 64*68
    float* sG    = sWd  + 64 * PAD;      // 64*68
    float* sKsum = sG   + 64 * PAD;      // 128
    float* sBvd  = sKsum + 128;          // 64
    const float4* g_part4 = (const float4*)g_part;

    const int bh = blockIdx.x, h = bh & 15, tid = threadIdx.x;

    #pragma unroll
    for (int t = 0; t < 16; t++) {
        int i = tid + t * 256; int k = i >> 6, c = i & 63;
        sWv[k * PAD + c] = wv_w[k * 1024 + h * 64 + c];
        sWd[k * PAD + c] = dense_w[(h * 64 + k) * 64 + c];
    }
    #pragma unroll
    for (int t = 0; t < 8; t++) {
        int idx = tid + t * 256;
        int x = idx >> 5, c8 = idx & 31;
        float4 s = make_float4(0.f, 0.f, 0.f, 0.f);
        for (int sl = 0; sl < NSPLIT; sl++) {
            float4 v = g_part4[((size_t)(sl * 64 + bh)) * 2048 + idx];
            s.x += v.x; s.y += v.y; s.z += v.z; s.w += v.w;
        }
        int row = (c8 < 16) ? x : (x + 64);
        int c4  = c8 & 15;
        *(float4*)&sC[row * PAD + c4 * 4] = s;
    }
    if (tid < 128) {
        float s = 0.f;
        for (int sl = 0; sl < NSPLIT; sl++) s += g_partKs[(sl * 64 + bh) * 128 + tid];
        sKsum[tid] = s;
        g_Ks[bh * 128 + tid] = s;
    }
    __syncthreads();

    const int r  = tid >> 2;
    const int c0 = (tid & 3) * 16;

    // G = Wv @ Wd
    {
        float a16[16];
        #pragma unroll
        for (int j = 0; j < 16; j++) a16[j] = 0.f;
        for (int kk = 0; kk < 64; kk++) {
            float a = sWv[r * PAD + kk];
            #pragma unroll
            for (int j = 0; j < 16; j++) a16[j] += a * sWd[kk * PAD + c0 + j];
        }
        #pragma unroll
        for (int j = 0; j < 16; j++) sG[r * PAD + c0 + j] = a16[j];
    }
    if (tid < 64) {
        float s = 0.f;
        for (int c = 0; c < 64; c++) s += wv_b[h * 64 + c] * sWd[c * PAD + tid];
        sBvd[tid] = s;
    }
    __syncthreads();

    // M/Mp = sC @ sG + ksum (outer) bvd -> g_Mst interleaved (free permute)
    {
        float m0[16], m1[16];
        #pragma unroll
        for (int j = 0; j < 16; j++) { m0[j] = 0.f; m1[j] = 0.f; }
        for (int kk = 0; kk < 64; kk++) {
            float a0 = sC[r * PAD + kk];
            float a1 = sC[(r + 64) * PAD + kk];
            #pragma unroll
            for (int j = 0; j < 16; j++) {
                float gv = sG[kk * PAD + c0 + j];
                m0[j] += a0 * gv; m1[j] += a1 * gv;
            }
        }
        float k0 = sKsum[r], k1 = sKsum[r + 64];
        #pragma unroll
        for (int j = 0; j < 16; j++) {
            m0[j] += k0 * sBvd[c0 + j];
            m1[j] += k1 * sBvd[c0 + j];
        }
        unsigned* dst = &g_Mst[(size_t)bh * 8192];
        #pragma unroll
        for (int j = 0; j < 16; j++) {
            int w0 = bpair2(r, c0 + j);   // even -> uint2-aligned
            *(uint2*)&dst[w0] = make_uint2(tf32c(m0[j]), tf32c(m1[j]));
        }
    }
}

// ===========================================================================
// Kernel 3 (tensor, tf32) — unchanged R13-proven version:
//   q = elu1(rawQ @ Wq_h + bq); den; o = q@M + w*(q@Mp)  [split GEMM, K=64,
//   both B fragments per (k,n) fetched with ONE LDS.128 from interleaved sB]
// ===========================================================================
__global__ __launch_bounds__(256, 2)
void out_kernel(const float4* __restrict__ query4,
                const float4* __restrict__ wq_w4, const float* __restrict__ wq_b,
                const float* __restrict__ dense_b, float* __restrict__ out)
{
    extern __shared__ unsigned smu[];
    unsigned* sQraw = smu;                  // 64 x 68  tf32 raw Q
    unsigned* sWq   = sQraw + 64 * 68;      // 64 x 72  tf32 Wq head slice
    unsigned* sB    = sWq   + 64 * 72;      // 8192     M/Mp interleaved pair layout
    unsigned* sQ    = sB    + 8192;         // 64 x 68  tf32 q (elu'd)
    float* sKs  = (float*)(sQ + 64 * 68);   // 128
    float* sWs  = sKs + 128;                // 64
    float* sQb  = sWs + 64;                 // 64
    float* sDot = sQb + 64;                 // 64 x 4

    const int b  = blockIdx.y;
    const int s0 = blockIdx.x * 64;
    const int tid = threadIdx.x;
    const int lane = tid & 31, wid = tid >> 5;
    const int g = lane >> 2, tig = lane & 3;
    const int mt = wid & 3, nh = wid >> 2;
    const int m0 = mt * 16, n0 = nh * 32;

    #pragma unroll
    for (int t = 0; t < 4; t++) {
        int idx = tid + t * 256; int r = idx >> 4, c4 = idx & 15;
        float4 q = query4[((size_t)(b * Sn + s0 + r)) * 16 + c4];
        *(uint4*)&sQraw[r * 68 + c4 * 4] = make_uint4(tf32c(q.x), tf32c(q.y), tf32c(q.z), tf32c(q.w));
    }
    if (tid < 64) {
        float ps = PIC * (float)(s0 + tid) / (float)Sn;
        sWs[tid] = __cosf(ps) + __sinf(ps);
    }

    float accO[4][4];
    #pragma unroll
    for (int nt = 0; nt < 4; nt++)
        #pragma unroll
        for (int j = 0; j < 4; j++) accO[nt][j] = 0.f;
    __syncthreads();

    const uint4* g_Mst4 = (const uint4*)g_Mst;

    for (int h = 0; h < Hn; h++) {
        const int bh = b * 16 + h;
        #pragma unroll
        for (int t = 0; t < 4; t++) {
            int idx = tid + t * 256; int d = idx >> 4, c4 = idx & 15;
            float4 w = wq_w4[d * 256 + h * 16 + c4];
            *(uint4*)&sWq[d * 72 + c4 * 4] = make_uint4(tf32c(w.x), tf32c(w.y), tf32c(w.z), tf32c(w.w));
        }
        #pragma unroll
        for (int t = 0; t < 8; t++) {
            int idx = tid + t * 256;
            *(uint4*)&sB[idx * 4] = g_Mst4[(size_t)bh * 2048 + idx];
        }
        if (tid < 128)      sKs[tid] = g_Ks[bh * 128 + tid];
        else if (tid < 192) sQb[tid - 128] = wq_b[h * 64 + (tid - 128)];
        __syncthreads();

        // ---- q projection mma ----
        float pc[4][4];
        #pragma unroll
        for (int nt = 0; nt < 4; nt++) {
            int col0 = n0 + 8 * nt + 2 * tig;
            pc[nt][0] = sQb[col0]; pc[nt][1] = sQb[col0 + 1];
            pc[nt][2] = sQb[col0]; pc[nt][3] = sQb[col0 + 1];
        }
        #pragma unroll
        for (int ks = 0; ks < 8; ks++) {
            int k0 = ks * 8;
            unsigned a0 = sQraw[(m0 + g)     * 68 + k0 + tig];
            unsigned a1 = sQraw[(m0 + g + 8) * 68 + k0 + tig];
            unsigned a2 = sQraw[(m0 + g)     * 68 + k0 + tig + 4];
            unsigned a3 = sQraw[(m0 + g + 8) * 68 + k0 + tig + 4];
            #pragma unroll
            for (int nt = 0; nt < 4; nt++) {
                int n = n0 + 8 * nt + g;
                unsigned b0 = sWq[(k0 + tig)     * 72 + n];
                unsigned b1 = sWq[(k0 + tig + 4) * 72 + n];
                mma8(pc[nt], a0, a1, a2, a3, b0, b1);
            }
        }

        // ---- elu, partial denominators, store q (K=64, no wq) ----
        {
            int r1 = (m0 + g) * 68, r2 = (m0 + g + 8) * 68;
            float d0a = 0.f, d1a = 0.f, d0b = 0.f, d1b = 0.f;
            #pragma unroll
            for (int nt = 0; nt < 4; nt++) {
                int col0 = n0 + 8 * nt + 2 * tig;
                float ks0 = sKs[col0],      ks1 = sKs[col0 + 1];
                float kp0 = sKs[64 + col0], kp1 = sKs[64 + col0 + 1];
                float v00 = elu1(pc[nt][0]), v01 = elu1(pc[nt][1]);
                float v10 = elu1(pc[nt][2]), v11 = elu1(pc[nt][3]);
                d0a += v00 * ks0 + v01 * ks1;  d1a += v00 * kp0 + v01 * kp1;
                d0b += v10 * ks0 + v11 * ks1;  d1b += v10 * kp0 + v11 * kp1;
                sQ[r1 + col0]     = tf32c(v00);
                sQ[r1 + col0 + 1] = tf32c(v01);
                sQ[r2 + col0]     = tf32c(v10);
                sQ[r2 + col0 + 1] = tf32c(v11);
            }
            d0a += __shfl_xor_sync(0xffffffffu, d0a, 1); d0a += __shfl_xor_sync(0xffffffffu, d0a, 2);
            d1a += __shfl_xor_sync(0xffffffffu, d1a, 1); d1a += __shfl_xor_sync(0xffffffffu, d1a, 2);
            d0b += __shfl_xor_sync(0xffffffffu, d0b, 1); d0b += __shfl_xor_sync(0xffffffffu, d0b, 2);
            d1b += __shfl_xor_sync(0xffffffffu, d1b, 1); d1b += __shfl_xor_sync(0xffffffffu, d1b, 2);
            if (tig == 0) {
                sDot[(m0 + g) * 4 + nh]         = d0a;
                sDot[(m0 + g) * 4 + 2 + nh]     = d1a;
                sDot[(m0 + g + 8) * 4 + nh]     = d0b;
                sDot[(m0 + g + 8) * 4 + 2 + nh] = d1b;
            }
        }
        __syncthreads();

        int r1 = m0 + g, r2 = m0 + g + 8;
        float w1 = sWs[r1], w2 = sWs[r2];
        float den1 = 1.0f / (sDot[r1 * 4] + sDot[r1 * 4 + 1]
                     + w1 * (sDot[r1 * 4 + 2] + sDot[r1 * 4 + 3]) + 1e-5f);
        float den2 = 1.0f / (sDot[r2 * 4] + sDot[r2 * 4 + 1]
                     + w2 * (sDot[r2 * 4 + 2] + sDot[r2 * 4 + 3]) + 1e-5f);
        float dnw1 = den1 * w1, dnw2 = den2 * w2;

        // ---- split o-GEMM: ocM = q@M, ocP = q@Mp (K=64, shared A, fused B LDS.128) ----
        float ocM[4][4], ocP[4][4];
        #pragma unroll
        for (int nt = 0; nt < 4; nt++)
            #pragma unroll
            for (int j = 0; j < 4; j++) { ocM[nt][j] = 0.f; ocP[nt][j] = 0.f; }
        #pragma unroll
        for (int ks = 0; ks < 8; ks++) {
            int k0 = ks * 8;
            unsigned a0 = sQ[(m0 + g)     * 68 + k0 + tig];
            unsigned a1 = sQ[(m0 + g + 8) * 68 + k0 + tig];
            unsigned a2 = sQ[(m0 + g)     * 68 + k0 + tig + 4];
            unsigned a3 = sQ[(m0 + g + 8) * 68 + k0 + tig + 4];
            #pragma unroll
            for (int nt = 0; nt < 4; nt++) {
                int n = n0 + 8 * nt + g;
                uint4 bb = *(const uint4*)&sB[(ks * 64 + n) * 16 + tig * 4];
                mma8(ocM[nt], a0, a1, a2, a3, bb.x, bb.z);
                mma8(ocP[nt], a0, a1, a2, a3, bb.y, bb.w);
            }
        }
        #pragma unroll
        for (int nt = 0; nt < 4; nt++) {
            accO[nt][0] += den1 * ocM[nt][0] + dnw1 * ocP[nt][0];
            accO[nt][1] += den1 * ocM[nt][1] + dnw1 * ocP[nt][1];
            accO[nt][2] += den2 * ocM[nt][2] + dnw2 * ocP[nt][2];
            accO[nt][3] += den2 * ocM[nt][3] + dnw2 * ocP[nt][3];
        }
        __syncthreads();
    }

    // ---- epilogue: + dense_b, vectorized float2 stores ----
    #pragma unroll
    for (int nt = 0; nt < 4; nt++) {
        int col0 = n0 + 8 * nt + 2 * tig;
        float2 db = *(const float2*)&dense_b[col0];
        size_t o1 = ((size_t)(b * Sn + s0 + m0 + g)) * 64 + col0;
        size_t o2 = ((size_t)(b * Sn + s0 + m0 + g + 8)) * 64 + col0;
        *(float2*)&out[o1] = make_float2(accO[nt][0] + db.x, accO[nt][1] + db.y);
        *(float2*)&out[o2] = make_float2(accO[nt][2] + db.x, accO[nt][3] + db.y);
    }
}

// ---------------------------------------------------------------------------
extern "C" void kernel_launch(void* const* d_in, const int* in_sizes, int n_in,
                              void* d_out, int out_size)
{
    const float4* query4  = (const float4*)d_in[0];
    const float4* key4    = (const float4*)d_in[1];
    const float4* value4  = (const float4*)d_in[2];
    // d_in[3] = attn_mask (unused by the math)
    const float4* wq_w4   = (const float4*)d_in[4];
    const float*  wq_b    = (const float*)d_in[5];
    const float4* wk_w4   = (const float4*)d_in[6];
    const float*  wk_b    = (const float*)d_in[7];
    const float*  wv_w    = (const float*)d_in[8];
    const float*  wv_b    = (const float*)d_in[9];
    const float*  dense_w = (const float*)d_in[10];
    const float*  dense_b = (const float*)d_in[11];
    float* out = (float*)d_out;

    constexpr int SM_KV  = (2304 * 3 + 4352 + 64 + 64 + 512) * 4;             // 47,360 B
    constexpr int SM_MP  = (128 * PAD + 3 * 64 * PAD + 128 + 64) * 4;         // 87,808 B
    constexpr int SM_OUT = (64*68 + 64*72 + 8192 + 64*68 + 128+64+64+256)*4;  // 88,064 B

    cudaFuncSetAttribute(kv_kernel,    cudaFuncAttributeMaxDynamicSharedMemorySize, SM_KV);
    cudaFuncSetAttribute(mprep_kernel, cudaFuncAttributeMaxDynamicSharedMemorySize, SM_MP);
    cudaFuncSetAttribute(out_kernel,   cudaFuncAttributeMaxDynamicSharedMemorySize, SM_OUT);

    kv_kernel   <<<dim3(BHn, NSPLIT), 256, SM_KV >>>(key4, value4, wk_w4, wk_b);
    mprep_kernel<<<BHn,               256, SM_MP >>>(wv_w, wv_b, dense_w);
    out_kernel  <<<dim3(Sn / 64, Bn), 256, SM_OUT>>>(query4, wq_w4, wq_b, dense_b, out);
}

// round 15
// speedup vs baseline: 1.6343x; 1.2336x over previous
#include <cuda_runtime.h>
#include <cuda_fp16.h>

// ---------------- problem constants ----------------
constexpr int Bn = 4;
constexpr int Sn = 4096;
constexpr int Hn = 16;
constexpr int BHn = 64;
constexpr int NSPLIT = 16;
constexpr int SCHUNK = Sn / NSPLIT;   // 256
constexpr int CH  = 64;               // s-rows per staged chunk
constexpr int NCH = SCHUNK / CH;      // 4
constexpr float PIC = 3.1415f;        // verbatim constant from reference

// ---------------- static device scratch ----------------
__device__ float    g_part  [NSPLIT * 64 * 8192];  // slot x bh x [64x128] fp32 (KV | KVp)
__device__ float    g_partKs[NSPLIT * 64 * 128];   // slot x bh x [ksum|kpsum]
__device__ unsigned g_Mst   [64 * 8192];           // bh x {M halves [64x64] ; Mp halves}
__device__ float    g_Ks    [64 * 128];            // bh x stacked [Ksum;Kpsum] fp32

// ---------------- helpers ----------------
__device__ __forceinline__ void mma16h(float* c,
    unsigned a0, unsigned a1, unsigned a2, unsigned a3, unsigned b0, unsigned b1)
{
    asm volatile(
        "mma.sync.aligned.m16n8k16.row.col.f32.f16.f16.f32 "
        "{%0,%1,%2,%3},{%4,%5,%6,%7},{%8,%9},{%0,%1,%2,%3};"
        : "+f"(c[0]), "+f"(c[1]), "+f"(c[2]), "+f"(c[3])
        : "r"(a0), "r"(a1), "r"(a2), "r"(a3), "r"(b0), "r"(b1));
}
__device__ __forceinline__ void ldsm4t(unsigned& r0, unsigned& r1, unsigned& r2, unsigned& r3,
                                       unsigned addr)
{
    asm volatile("ldmatrix.sync.aligned.m8n8.x4.trans.shared.b16 {%0,%1,%2,%3}, [%4];"
        : "=r"(r0), "=r"(r1), "=r"(r2), "=r"(r3) : "r"(addr));
}
__device__ __forceinline__ unsigned h2u(float a, float b) {
    __half2 h = __floats2half2_rn(a, b);
    return *reinterpret_cast<unsigned*>(&h);
}
__device__ __forceinline__ float elu1(float v) { return v > 0.f ? v + 1.f : __expf(v); }

// ===========================================================================
// Kernel 1 (tensor, fp16 operands) — R14-proven version (clock probe):
//   kp = elu1(rawK @ Wk_h + bk)        [mma f16 k16; B via ldmatrix.x4.trans]
//   C[64x128] += kp^T @ [V | sinV]     [mma f16 k16; B via ldmatrix.x4.trans]
// ===========================================================================
__global__ __launch_bounds__(256, 2)
void kv_kernel(const float4* __restrict__ key4, const float4* __restrict__ value4,
               const float4* __restrict__ wk_w4, const float* __restrict__ wk_b)
{
    extern __shared__ unsigned smu[];
    unsigned* hWkw = smu;                 // Wk  [k=d][n] halves, stride 72h (36w): 2304w
    unsigned* hKw  = hWkw + 2304;         // rawK [s][d] halves, stride 72h: 2304w
    unsigned* hVw  = hKw  + 2304;         // [V|sinV] [s][z] halves, stride 136h (68w): 4352w
    unsigned* hAw  = hVw  + 4352;         // kp^T [x][s] halves, stride 72h: 2304w
    float* sSin  = (float*)(hAw + 2304);  // 64
    float* sBias = sSin + 64;             // 64
    float* sKred = sBias + 64;            // 4 x 128
    __half* hAh = (__half*)hAw;

    const int bh = blockIdx.x, split = blockIdx.y;
    const int b  = bh >> 4,   h     = bh & 15;
    const int tid = threadIdx.x;
    const int lane = tid & 31, wid = tid >> 5;
    const int g = lane >> 2, tig = lane & 3;
    const int sbase = split * SCHUNK;
    const int rowp = ((lane >> 3) & 1) * 8 + (lane & 7);
    const int colp = (lane >> 4) * 8;

    const unsigned wkBase = (unsigned)__cvta_generic_to_shared(hWkw);
    const unsigned vBase  = (unsigned)__cvta_generic_to_shared(hVw);

    // ---- stage Wk [k][n] halves + bias ----
    #pragma unroll
    for (int t = 0; t < 4; t++) {
        int idx = tid + t * 256; int d = idx >> 4, c4 = idx & 15;
        float4 w = wk_w4[d * 256 + h * 16 + c4];
        *(uint2*)&hWkw[d * 36 + 2 * c4] = make_uint2(h2u(w.x, w.y), h2u(w.z, w.w));
    }
    if (tid < 64) sBias[tid] = wk_b[h * 64 + tid];

    // ---- stage chunk 0 ----
    #pragma unroll
    for (int t = 0; t < 4; t++) {
        int idx = tid + t * 256; int r = idx >> 4, c4 = idx & 15;
        size_t gi = ((size_t)(b * Sn + sbase + r)) * 16 + c4;
        float4 k = key4[gi], v = value4[gi];
        *(uint2*)&hKw[r * 36 + 2 * c4] = make_uint2(h2u(k.x, k.y), h2u(k.z, k.w));
        float sn = __sinf(PIC * (float)(sbase + r) / (float)Sn);
        *(uint2*)&hVw[r * 68 + 2 * c4]      = make_uint2(h2u(v.x, v.y), h2u(v.z, v.w));
        *(uint2*)&hVw[r * 68 + 32 + 2 * c4] = make_uint2(h2u(v.x*sn, v.y*sn), h2u(v.z*sn, v.w*sn));
    }
    if (tid < 64) sSin[tid] = __sinf(PIC * (float)(sbase + tid) / (float)Sn);
    __syncthreads();

    const int m0p = (wid & 3) * 16;
    const int n0p = (wid >> 2) * 32;
    const int x0 = (wid & 1) * 32;
    const int z0 = (wid >> 1) * 32;

    float acc[2][4][4];
    #pragma unroll
    for (int i = 0; i < 2; i++)
        #pragma unroll
        for (int nt = 0; nt < 4; nt++)
            #pragma unroll
            for (int j = 0; j < 4; j++) acc[i][nt][j] = 0.f;
    float kc[4][2], kpc[4][2];
    #pragma unroll
    for (int nt = 0; nt < 4; nt++) { kc[nt][0]=kc[nt][1]=kpc[nt][0]=kpc[nt][1]=0.f; }

    for (int cc = 0; cc < NCH; cc++) {
        // ---- projection mma (f16 k16) ----
        float pc[4][4];
        #pragma unroll
        for (int nt = 0; nt < 4; nt++) {
            int col0 = n0p + 8 * nt + 2 * tig;
            pc[nt][0] = sBias[col0]; pc[nt][1] = sBias[col0 + 1];
            pc[nt][2] = sBias[col0]; pc[nt][3] = sBias[col0 + 1];
        }
        #pragma unroll
        for (int ks = 0; ks < 4; ks++) {
            int kw = ks * 8;
            unsigned a0 = hKw[(m0p + g)     * 36 + kw + tig];
            unsigned a1 = hKw[(m0p + g + 8) * 36 + kw + tig];
            unsigned a2 = hKw[(m0p + g)     * 36 + kw + tig + 4];
            unsigned a3 = hKw[(m0p + g + 8) * 36 + kw + tig + 4];
            #pragma unroll
            for (int p = 0; p < 2; p++) {
                unsigned b0, b1, b2, b3;
                unsigned ad = wkBase + ((16 * ks + rowp) * 72 + n0p + 16 * p + colp) * 2;
                ldsm4t(b0, b1, b2, b3, ad);
                mma16h(pc[2 * p],     a0, a1, a2, a3, b0, b1);
                mma16h(pc[2 * p + 1], a0, a1, a2, a3, b2, b3);
            }
        }

        // ---- elu + half-store kp^T + fp32 ksum FMA ----
        {
            int s1 = m0p + g, s2 = m0p + g + 8;
            float sn1 = sSin[s1], sn2 = sSin[s2];
            #pragma unroll
            for (int nt = 0; nt < 4; nt++) {
                int col0 = n0p + 8 * nt + 2 * tig;
                float v00 = elu1(pc[nt][0]), v01 = elu1(pc[nt][1]);
                float v10 = elu1(pc[nt][2]), v11 = elu1(pc[nt][3]);
                kc [nt][0] += v00 + v10;           kc [nt][1] += v01 + v11;
                kpc[nt][0] += v00*sn1 + v10*sn2;   kpc[nt][1] += v01*sn1 + v11*sn2;
                hAh[(col0)     * 72 + s1] = __float2half_rn(v00);
                hAh[(col0 + 1) * 72 + s1] = __float2half_rn(v01);
                hAh[(col0)     * 72 + s2] = __float2half_rn(v10);
                hAh[(col0 + 1) * 72 + s2] = __float2half_rn(v11);
            }
        }
        __syncthreads();

        // ---- accumulation mma (f16 k16) ----
        #pragma unroll
        for (int ks = 0; ks < 4; ks++) {
            int kw = ks * 8;
            unsigned a[2][4];
            #pragma unroll
            for (int i = 0; i < 2; i++) {
                int xr = x0 + 16 * i + g;
                a[i][0] = hAw[xr       * 36 + kw + tig];
                a[i][1] = hAw[(xr + 8) * 36 + kw + tig];
                a[i][2] = hAw[xr       * 36 + kw + tig + 4];
                a[i][3] = hAw[(xr + 8) * 36 + kw + tig + 4];
            }
            #pragma unroll
            for (int p = 0; p < 2; p++) {
                unsigned b0, b1, b2, b3;
                unsigned ad = vBase + ((16 * ks + rowp) * 136 + z0 + 16 * p + colp) * 2;
                ldsm4t(b0, b1, b2, b3, ad);
                #pragma unroll
                for (int i = 0; i < 2; i++) {
                    mma16h(acc[i][2 * p],     a[i][0], a[i][1], a[i][2], a[i][3], b0, b1);
                    mma16h(acc[i][2 * p + 1], a[i][0], a[i][1], a[i][2], a[i][3], b2, b3);
                }
            }
        }
        __syncthreads();

        // ---- restage next chunk ----
        if (cc + 1 < NCH) {
            int scs = sbase + (cc + 1) * CH;
            #pragma unroll
            for (int t = 0; t < 4; t++) {
                int idx = tid + t * 256; int r = idx >> 4, c4 = idx & 15;
                size_t gi = ((size_t)(b * Sn + scs + r)) * 16 + c4;
                float4 k = key4[gi], v = value4[gi];
                *(uint2*)&hKw[r * 36 + 2 * c4] = make_uint2(h2u(k.x, k.y), h2u(k.z, k.w));
                float sn = __sinf(PIC * (float)(scs + r) / (float)Sn);
                *(uint2*)&hVw[r * 68 + 2 * c4]      = make_uint2(h2u(v.x, v.y), h2u(v.z, v.w));
                *(uint2*)&hVw[r * 68 + 32 + 2 * c4] = make_uint2(h2u(v.x*sn, v.y*sn), h2u(v.z*sn, v.w*sn));
            }
            if (tid < 64) sSin[tid] = __sinf(PIC * (float)(scs + tid) / (float)Sn);
            __syncthreads();
        }
    }

    // ---- write fp32 C partials ----
    {
        size_t base = ((size_t)(split * 64 + bh)) * 8192;
        #pragma unroll
        for (int i = 0; i < 2; i++)
            #pragma unroll
            for (int nt = 0; nt < 4; nt++) {
                int x = x0 + 16 * i + g;
                int z = z0 + 8 * nt + 2 * tig;
                *(float2*)&g_part[base + (size_t)x       * 128 + z] = make_float2(acc[i][nt][0], acc[i][nt][1]);
                *(float2*)&g_part[base + (size_t)(x + 8) * 128 + z] = make_float2(acc[i][nt][2], acc[i][nt][3]);
            }
    }

    // ---- ksum reduce ----
    #pragma unroll
    for (int off = 4; off <= 16; off <<= 1)
        #pragma unroll
        for (int nt = 0; nt < 4; nt++)
            #pragma unroll
            for (int e = 0; e < 2; e++) {
                kc [nt][e] += __shfl_xor_sync(0xffffffffu, kc [nt][e], off);
                kpc[nt][e] += __shfl_xor_sync(0xffffffffu, kpc[nt][e], off);
            }
    if (g == 0) {
        int mt = wid & 3;
        #pragma unroll
        for (int nt = 0; nt < 4; nt++)
            #pragma unroll
            for (int e = 0; e < 2; e++) {
                int x = n0p + 8 * nt + 2 * tig + e;
                sKred[mt * 128 + x]      = kc [nt][e];
                sKred[mt * 128 + 64 + x] = kpc[nt][e];
            }
    }
    __syncthreads();
    if (tid < 128)
        g_partKs[(split * 64 + bh) * 128 + tid] =
            sKred[tid] + sKred[128 + tid] + sKred[256 + tid] + sKred[384 + tid];
}

// ===========================================================================
// Kernel 2: per bh — reduce partials, fold V-proj + dense:
//   M/Mp -> g_Mst as PACKED HALF matrices: [bh][{M,Mp}][k=64][n=64] halves.
// ===========================================================================
constexpr int PAD = 68;
__global__ __launch_bounds__(256)
void mprep_kernel(const float* __restrict__ wv_w, const float* __restrict__ wv_b,
                  const float* __restrict__ dense_w)
{
    extern __shared__ float sm[];
    float* sC    = sm;                   // 128*68 (stacked rows [KV;KVp])
    float* sWv   = sC   + 128 * PAD;     // 64*68
    float* sWd   = sWv  + 64 * PAD;      // 64*68
    float* sG    = sWd  + 64 * PAD;      // 64*68
    float* sKsum = sG   + 64 * PAD;      // 128
    float* sBvd  = sKsum + 128;          // 64
    const float4* g_part4 = (const float4*)g_part;

    const int bh = blockIdx.x, h = bh & 15, tid = threadIdx.x;

    #pragma unroll
    for (int t = 0; t < 16; t++) {
        int i = tid + t * 256; int k = i >> 6, c = i & 63;
        sWv[k * PAD + c] = wv_w[k * 1024 + h * 64 + c];
        sWd[k * PAD + c] = dense_w[(h * 64 + k) * 64 + c];
    }
    #pragma unroll
    for (int t = 0; t < 8; t++) {
        int idx = tid + t * 256;
        int x = idx >> 5, c8 = idx & 31;
        float4 s = make_float4(0.f, 0.f, 0.f, 0.f);
        for (int sl = 0; sl < NSPLIT; sl++) {
            float4 v = g_part4[((size_t)(sl * 64 + bh)) * 2048 + idx];
            s.x += v.x; s.y += v.y; s.z += v.z; s.w += v.w;
        }
        int row = (c8 < 16) ? x : (x + 64);
        int c4  = c8 & 15;
        *(float4*)&sC[row * PAD + c4 * 4] = s;
    }
    if (tid < 128) {
        float s = 0.f;
        for (int sl = 0; sl < NSPLIT; sl++) s += g_partKs[(sl * 64 + bh) * 128 + tid];
        sKsum[tid] = s;
        g_Ks[bh * 128 + tid] = s;
    }
    __syncthreads();

    const int r  = tid >> 2;
    const int c0 = (tid & 3) * 16;

    // G = Wv @ Wd
    {
        float a16[16];
        #pragma unroll
        for (int j = 0; j < 16; j++) a16[j] = 0.f;
        for (int kk = 0; kk < 64; kk++) {
            float a = sWv[r * PAD + kk];
            #pragma unroll
            for (int j = 0; j < 16; j++) a16[j] += a * sWd[kk * PAD + c0 + j];
        }
        #pragma unroll
        for (int j = 0; j < 16; j++) sG[r * PAD + c0 + j] = a16[j];
    }
    if (tid < 64) {
        float s = 0.f;
        for (int c = 0; c < 64; c++) s += wv_b[h * 64 + c] * sWd[c * PAD + tid];
        sBvd[tid] = s;
    }
    __syncthreads();

    // M/Mp = sC @ sG + ksum (outer) bvd -> packed half matrices
    {
        float m0[16], m1[16];
        #pragma unroll
        for (int j = 0; j < 16; j++) { m0[j] = 0.f; m1[j] = 0.f; }
        for (int kk = 0; kk < 64; kk++) {
            float a0 = sC[r * PAD + kk];
            float a1 = sC[(r + 64) * PAD + kk];
            #pragma unroll
            for (int j = 0; j < 16; j++) {
                float gv = sG[kk * PAD + c0 + j];
                m0[j] += a0 * gv; m1[j] += a1 * gv;
            }
        }
        float k0 = sKsum[r], k1 = sKsum[r + 64];
        #pragma unroll
        for (int j = 0; j < 16; j++) {
            m0[j] += k0 * sBvd[c0 + j];
            m1[j] += k1 * sBvd[c0 + j];
        }
        // word layout per bh: [0..2047]=M halves ([k=64][n=64], 32w/row),
        //                     [2048..4095]=Mp halves.
        unsigned* dstW = &g_Mst[(size_t)bh * 4096];
        #pragma unroll
        for (int j = 0; j < 16; j += 2) {
            dstW[r * 32 + (c0 + j) / 2]        = h2u(m0[j], m0[j + 1]);
            dstW[2048 + r * 32 + (c0 + j) / 2] = h2u(m1[j], m1[j + 1]);
        }
    }
}

// ===========================================================================
// Kernel 3 (tensor, fp16): per (b, 64-row s-tile), loop heads:
//   q = elu1(rawQ @ Wq_h + bq)    [mma f16 k16; Wq via ldmatrix.x4.trans]
//   den (fp32); o = q@M + w*(q@Mp) [mma f16 k16; M/Mp via ldmatrix.x4.trans]
// ===========================================================================
__global__ __launch_bounds__(256, 2)
void out_kernel(const float4* __restrict__ query4,
                const float4* __restrict__ wq_w4, const float* __restrict__ wq_b,
                const float* __restrict__ dense_b, float* __restrict__ out)
{
    extern __shared__ unsigned smu[];
    unsigned* hQraw = smu;                 // rawQ [s][d] halves, stride 72h: 2304w
    unsigned* hWq   = hQraw + 2304;        // Wq [d][n] halves, stride 72h: 2304w
    unsigned* hM    = hWq   + 2304;        // M  [k][n] halves, stride 72h: 2304w
    unsigned* hMp   = hM    + 2304;        // Mp [k][n] halves, stride 72h: 2304w
    unsigned* hQ    = hMp   + 2304;        // q  [s][x] halves, stride 72h: 2304w
    float* sKs  = (float*)(hQ + 2304);     // 128
    float* sWs  = sKs + 128;               // 64
    float* sQb  = sWs + 64;                // 64
    float* sDot = sQb + 64;                // 64 x 4
    __half* hQh = (__half*)hQ;

    const int b  = blockIdx.y;
    const int s0 = blockIdx.x * 64;
    const int tid = threadIdx.x;
    const int lane = tid & 31, wid = tid >> 5;
    const int g = lane >> 2, tig = lane & 3;
    const int mt = wid & 3, nh = wid >> 2;
    const int m0 = mt * 16, n0 = nh * 32;
    const int rowp = ((lane >> 3) & 1) * 8 + (lane & 7);
    const int colp = (lane >> 4) * 8;

    const unsigned wqBase = (unsigned)__cvta_generic_to_shared(hWq);
    const unsigned mBase  = (unsigned)__cvta_generic_to_shared(hM);
    const unsigned mpBase = (unsigned)__cvta_generic_to_shared(hMp);

    // stage raw Q halves (once per CTA)
    #pragma unroll
    for (int t = 0; t < 4; t++) {
        int idx = tid + t * 256; int r = idx >> 4, c4 = idx & 15;
        float4 q = query4[((size_t)(b * Sn + s0 + r)) * 16 + c4];
        *(uint2*)&hQraw[r * 36 + 2 * c4] = make_uint2(h2u(q.x, q.y), h2u(q.z, q.w));
    }
    if (tid < 64) {
        float ps = PIC * (float)(s0 + tid) / (float)Sn;
        sWs[tid] = __cosf(ps) + __sinf(ps);
    }

    float accO[4][4];
    #pragma unroll
    for (int nt = 0; nt < 4; nt++)
        #pragma unroll
        for (int j = 0; j < 4; j++) accO[nt][j] = 0.f;
    __syncthreads();

    for (int h = 0; h < Hn; h++) {
        const int bh = b * 16 + h;
        // ---- stage Wq halves ----
        #pragma unroll
        for (int t = 0; t < 4; t++) {
            int idx = tid + t * 256; int d = idx >> 4, c4 = idx & 15;
            float4 w = wq_w4[d * 256 + h * 16 + c4];
            *(uint2*)&hWq[d * 36 + 2 * c4] = make_uint2(h2u(w.x, w.y), h2u(w.z, w.w));
        }
        // ---- stage M/Mp half matrices (padded rows) ----
        {
            const uint2* src2 = (const uint2*)&g_Mst[(size_t)bh * 4096];
            #pragma unroll
            for (int t = 0; t < 8; t++) {
                int idx2 = tid + t * 256;             // 0..2047 uint2
                int mat = idx2 >> 10;                 // 0=M, 1=Mp
                int k   = (idx2 >> 4) & 63;
                int c2  = idx2 & 15;
                uint2 v = src2[idx2];
                unsigned* dst = mat ? hMp : hM;
                *(uint2*)&dst[k * 36 + 2 * c2] = v;
            }
        }
        if (tid < 128)      sKs[tid] = g_Ks[bh * 128 + tid];
        else if (tid < 192) sQb[tid - 128] = wq_b[h * 64 + (tid - 128)];
        __syncthreads();

        // ---- q projection mma (f16 k16) ----
        float pc[4][4];
        #pragma unroll
        for (int nt = 0; nt < 4; nt++) {
            int col0 = n0 + 8 * nt + 2 * tig;
            pc[nt][0] = sQb[col0]; pc[nt][1] = sQb[col0 + 1];
            pc[nt][2] = sQb[col0]; pc[nt][3] = sQb[col0 + 1];
        }
        #pragma unroll
        for (int ks = 0; ks < 4; ks++) {
            int kw = ks * 8;
            unsigned a0 = hQraw[(m0 + g)     * 36 + kw + tig];
            unsigned a1 = hQraw[(m0 + g + 8) * 36 + kw + tig];
            unsigned a2 = hQraw[(m0 + g)     * 36 + kw + tig + 4];
            unsigned a3 = hQraw[(m0 + g + 8) * 36 + kw + tig + 4];
            #pragma unroll
            for (int p = 0; p < 2; p++) {
                unsigned b0, b1, b2, b3;
                unsigned ad = wqBase + ((16 * ks + rowp) * 72 + n0 + 16 * p + colp) * 2;
                ldsm4t(b0, b1, b2, b3, ad);
                mma16h(pc[2 * p],     a0, a1, a2, a3, b0, b1);
                mma16h(pc[2 * p + 1], a0, a1, a2, a3, b2, b3);
            }
        }

        // ---- elu, partial denominators, half-store q [s][x] ----
        {
            int r1 = (m0 + g) * 72, r2 = (m0 + g + 8) * 72;
            float d0a = 0.f, d1a = 0.f, d0b = 0.f, d1b = 0.f;
            #pragma unroll
            for (int nt = 0; nt < 4; nt++) {
                int col0 = n0 + 8 * nt + 2 * tig;
                float ks0 = sKs[col0],      ks1 = sKs[col0 + 1];
                float kp0 = sKs[64 + col0], kp1 = sKs[64 + col0 + 1];
                float v00 = elu1(pc[nt][0]), v01 = elu1(pc[nt][1]);
                float v10 = elu1(pc[nt][2]), v11 = elu1(pc[nt][3]);
                d0a += v00 * ks0 + v01 * ks1;  d1a += v00 * kp0 + v01 * kp1;
                d0b += v10 * ks0 + v11 * ks1;  d1b += v10 * kp0 + v11 * kp1;
                hQh[r1 + col0]     = __float2half_rn(v00);
                hQh[r1 + col0 + 1] = __float2half_rn(v01);
                hQh[r2 + col0]     = __float2half_rn(v10);
                hQh[r2 + col0 + 1] = __float2half_rn(v11);
            }
            d0a += __shfl_xor_sync(0xffffffffu, d0a, 1); d0a += __shfl_xor_sync(0xffffffffu, d0a, 2);
            d1a += __shfl_xor_sync(0xffffffffu, d1a, 1); d1a += __shfl_xor_sync(0xffffffffu, d1a, 2);
            d0b += __shfl_xor_sync(0xffffffffu, d0b, 1); d0b += __shfl_xor_sync(0xffffffffu, d0b, 2);
            d1b += __shfl_xor_sync(0xffffffffu, d1b, 1); d1b += __shfl_xor_sync(0xffffffffu, d1b, 2);
            if (tig == 0) {
                sDot[(m0 + g) * 4 + nh]         = d0a;
                sDot[(m0 + g) * 4 + 2 + nh]     = d1a;
                sDot[(m0 + g + 8) * 4 + nh]     = d0b;
                sDot[(m0 + g + 8) * 4 + 2 + nh] = d1b;
            }
        }
        __syncthreads();

        int r1 = m0 + g, r2 = m0 + g + 8;
        float w1 = sWs[r1], w2 = sWs[r2];
        float den1 = 1.0f / (sDot[r1 * 4] + sDot[r1 * 4 + 1]
                     + w1 * (sDot[r1 * 4 + 2] + sDot[r1 * 4 + 3]) + 1e-5f);
        float den2 = 1.0f / (sDot[r2 * 4] + sDot[r2 * 4 + 1]
                     + w2 * (sDot[r2 * 4 + 2] + sDot[r2 * 4 + 3]) + 1e-5f);
        float dnw1 = den1 * w1, dnw2 = den2 * w2;

        // ---- split o-GEMM (f16 k16): ocM = q@M, ocP = q@Mp ----
        float ocM[4][4], ocP[4][4];
        #pragma unroll
        for (int nt = 0; nt < 4; nt++)
            #pragma unroll
            for (int j = 0; j < 4; j++) { ocM[nt][j] = 0.f; ocP[nt][j] = 0.f; }
        #pragma unroll
        for (int ks = 0; ks < 4; ks++) {
            int kw = ks * 8;
            unsigned a0 = hQ[(m0 + g)     * 36 + kw + tig];
            unsigned a1 = hQ[(m0 + g + 8) * 36 + kw + tig];
            unsigned a2 = hQ[(m0 + g)     * 36 + kw + tig + 4];
            unsigned a3 = hQ[(m0 + g + 8) * 36 + kw + tig + 4];
            #pragma unroll
            for (int p = 0; p < 2; p++) {
                unsigned rowoff = ((16 * ks + rowp) * 72 + n0 + 16 * p + colp) * 2;
                unsigned b0, b1, b2, b3;
                ldsm4t(b0, b1, b2, b3, mBase + rowoff);
                mma16h(ocM[2 * p],     a0, a1, a2, a3, b0, b1);
                mma16h(ocM[2 * p + 1], a0, a1, a2, a3, b2, b3);
                ldsm4t(b0, b1, b2, b3, mpBase + rowoff);
                mma16h(ocP[2 * p],     a0, a1, a2, a3, b0, b1);
                mma16h(ocP[2 * p + 1], a0, a1, a2, a3, b2, b3);
            }
        }
        #pragma unroll
        for (int nt = 0; nt < 4; nt++) {
            accO[nt][0] += den1 * ocM[nt][0] + dnw1 * ocP[nt][0];
            accO[nt][1] += den1 * ocM[nt][1] + dnw1 * ocP[nt][1];
            accO[nt][2] += den2 * ocM[nt][2] + dnw2 * ocP[nt][2];
            accO[nt][3] += den2 * ocM[nt][3] + dnw2 * ocP[nt][3];
        }
        __syncthreads();
    }

    // ---- epilogue: + dense_b, vectorized float2 stores ----
    #pragma unroll
    for (int nt = 0; nt < 4; nt++) {
        int col0 = n0 + 8 * nt + 2 * tig;
        float2 db = *(const float2*)&dense_b[col0];
        size_t o1 = ((size_t)(b * Sn + s0 + m0 + g)) * 64 + col0;
        size_t o2 = ((size_t)(b * Sn + s0 + m0 + g + 8)) * 64 + col0;
        *(float2*)&out[o1] = make_float2(accO[nt][0] + db.x, accO[nt][1] + db.y);
        *(float2*)&out[o2] = make_float2(accO[nt][2] + db.x, accO[nt][3] + db.y);
    }
}

// ---------------------------------------------------------------------------
extern "C" void kernel_launch(void* const* d_in, const int* in_sizes, int n_in,
                              void* d_out, int out_size)
{
    const float4* query4  = (const float4*)d_in[0];
    const float4* key4    = (const float4*)d_in[1];
    const float4* value4  = (const float4*)d_in[2];
    // d_in[3] = attn_mask (unused by the math)
    const float4* wq_w4   = (const float4*)d_in[4];
    const float*  wq_b    = (const float*)d_in[5];
    const float4* wk_w4   = (const float4*)d_in[6];
    const float*  wk_b    = (const float*)d_in[7];
    const float*  wv_w    = (const float*)d_in[8];
    const float*  wv_b    = (const float*)d_in[9];
    const float*  dense_w = (const float*)d_in[10];
    const float*  dense_b = (const float*)d_in[11];
    float* out = (float*)d_out;

    constexpr int SM_KV  = (2304 * 3 + 4352 + 64 + 64 + 512) * 4;       // 47,360 B
    constexpr int SM_MP  = (128 * PAD + 3 * 64 * PAD + 128 + 64) * 4;   // 87,808 B
    constexpr int SM_OUT = (2304 * 5 + 128 + 64 + 64 + 256) * 4;        // 48,128 B

    cudaFuncSetAttribute(kv_kernel,    cudaFuncAttributeMaxDynamicSharedMemorySize, SM_KV);
    cudaFuncSetAttribute(mprep_kernel, cudaFuncAttributeMaxDynamicSharedMemorySize, SM_MP);
    cudaFuncSetAttribute(out_kernel,   cudaFuncAttributeMaxDynamicSharedMemorySize, SM_OUT);

    kv_kernel   <<<dim3(BHn, NSPLIT), 256, SM_KV >>>(key4, value4, wk_w4, wk_b);
    mprep_kernel<<<BHn,               256, SM_MP >>>(wv_w, wv_b, dense_w);
    out_kernel  <<<dim3(Sn / 64, Bn), 256, SM_OUT>>>(query4, wq_w4, wq_b, dense_b, out);
}